// round 5
// baseline (speedup 1.0000x reference)
#include <cuda_runtime.h>
#include <cuda_fp16.h>
#include <math.h>
#include <stdint.h>

// Problem constants
#define BB   2
#define SS   1024
#define DD   768
#define HH   12
#define DHH  64
#define LL   6
#define FF   3072
#define RELV 32
#define NROW (BB*SS)

// Weight-plane offsets (in elements)
#define WDD  (LL*DD*DD)      // 3538944
#define WDF  (LL*DD*FF)      // 14155776
#define OFF_WQ 0
#define OFF_WK (WDD)
#define OFF_WV (2*WDD)
#define OFF_WO (3*WDD)
#define OFF_W1 (4*WDD)
#define OFF_W2 (4*WDD + WDF)
#define WTOT   (4*WDD + 2*WDF)

// ---------------------------------------------------------------------------
// Scratch (device globals)
// ---------------------------------------------------------------------------
__device__ float g_x  [NROW*DD];
__device__ float g_rel[(size_t)BB*HH*SS*RELV];
__device__ __align__(16) __half g_hh [NROW*DD];
__device__ __align__(16) __half g_hl [NROW*DD];
__device__ __align__(16) __half g_qh [NROW*DD];
__device__ __align__(16) __half g_ql [NROW*DD];
__device__ __align__(16) __half g_kh [NROW*DD];
__device__ __align__(16) __half g_kl [NROW*DD];
__device__ __align__(16) __half g_vh [NROW*DD];
__device__ __align__(16) __half g_ch [NROW*DD];
__device__ __align__(16) __half g_cl [NROW*DD];
__device__ __align__(16) __half g_ffh[(size_t)NROW*FF];
__device__ __align__(16) __half g_ffl[(size_t)NROW*FF];
__device__ __align__(16) __half g_wh [WTOT];
__device__ __align__(16) __half g_wl [WTOT];

// ---------------------------------------------------------------------------
// helpers
// ---------------------------------------------------------------------------
__device__ __forceinline__ void h_split(float v, __half& hi, __half& lo) {
    hi = __float2half_rn(v);
    lo = __float2half_rn(v - __half2float(hi));
}

__device__ __forceinline__ uint32_t pack2(__half a, __half b) {
    __half2 t = __halves2half2(a, b);
    return *reinterpret_cast<uint32_t*>(&t);
}

__device__ __forceinline__ uint32_t ldh2(const __half* p) {
    return *reinterpret_cast<const uint32_t*>(p);
}

__device__ __forceinline__ void mma_f16(float c[4], uint32_t a0, uint32_t a1,
                                        uint32_t a2, uint32_t a3,
                                        uint32_t b0, uint32_t b1) {
    asm volatile(
        "mma.sync.aligned.m16n8k16.row.col.f32.f16.f16.f32 "
        "{%0,%1,%2,%3},{%4,%5,%6,%7},{%8,%9},{%0,%1,%2,%3};"
        : "+f"(c[0]), "+f"(c[1]), "+f"(c[2]), "+f"(c[3])
        : "r"(a0), "r"(a1), "r"(a2), "r"(a3), "r"(b0), "r"(b1));
}

__device__ __forceinline__ void mma_f16a(float c[4], const uint32_t a[4],
                                         uint32_t b0, uint32_t b1) {
    mma_f16(c, a[0], a[1], a[2], a[3], b0, b1);
}

__device__ __forceinline__ void ldsm4t(uint32_t& r0, uint32_t& r1,
                                       uint32_t& r2, uint32_t& r3, uint32_t a) {
    asm volatile("ldmatrix.sync.aligned.m8n8.x4.trans.shared.b16 {%0,%1,%2,%3}, [%4];"
                 : "=r"(r0), "=r"(r1), "=r"(r2), "=r"(r3) : "r"(a));
}

__device__ __forceinline__ float gelu_tanh(float v) {
    float u = 0.7978845608028654f * (v + 0.044715f * v * v * v);
    return 0.5f * v * (1.0f + tanhf(u));
}

// ---------------------------------------------------------------------------
// split kernel: fp32 -> (hi,lo) half planes, float4 granularity
// ---------------------------------------------------------------------------
__global__ void split_kernel(const float* __restrict__ s,
                             __half* __restrict__ hi, __half* __restrict__ lo,
                             int n4)
{
    int i = blockIdx.x * 256 + threadIdx.x;
    if (i >= n4) return;
    float4 v = reinterpret_cast<const float4*>(s)[i];
    __half h0, h1, h2, h3, l0, l1, l2, l3;
    h_split(v.x, h0, l0); h_split(v.y, h1, l1);
    h_split(v.z, h2, l2); h_split(v.w, h3, l3);
    uint2 ph, pl;
    ph.x = pack2(h0, h1); ph.y = pack2(h2, h3);
    pl.x = pack2(l0, l1); pl.y = pack2(l2, l3);
    reinterpret_cast<uint2*>(hi)[i] = ph;
    reinterpret_cast<uint2*>(lo)[i] = pl;
}

// ---------------------------------------------------------------------------
// GEMM core, pre-split halves. C = A@B + epilogue.
// A planes [M,K], B planes [K,N]. fp16x3: Ah.Bh + Al.Bh + Ah.Bl.
// EPI: 0=bias, 1=bias+gelu, 2=bias+residual
// OUT: 0=fp32, 1=hi/lo halves, 2=single half
// ---------------------------------------------------------------------------
template<int BM, int BN, int WM, int WN, int EPI, int OUT>
__device__ __forceinline__ void gemm_core(
    const __half* __restrict__ Agh, const __half* __restrict__ Agl, int lda,
    const __half* __restrict__ Bgh, const __half* __restrict__ Bgl, int ldb,
    const float* __restrict__ bias,
    const float* __restrict__ R, int ldr,
    float* __restrict__ Cf, __half* __restrict__ Ch, __half* __restrict__ Cl,
    int ldc, int K, int m0, int n0)
{
    constexpr int NWN = BN / WN;
    constexpr int NMT = WM / 16;
    constexpr int NNT = WN / 8;
    constexpr int NA4 = (BM * 16) / 1024;   // uint2 loads per thread (A, each plane)
    constexpr int NB4 = (BN * 16) / 1024;
    constexpr int AKP = 24;
    constexpr int BNP = BN + 8;
    constexpr int ASZ = BM * AKP;
    constexpr int BSZ = 16 * BNP;

    __shared__ __align__(16) __half sh[2 * ASZ + 2 * BSZ];
    __half* Ash = sh;
    __half* Asl = sh + ASZ;
    __half* Bsh = sh + 2 * ASZ;
    __half* Bsl = sh + 2 * ASZ + BSZ;

    const int tid  = threadIdx.x;
    const int lane = tid & 31;
    const int wid  = tid >> 5;
    const int g    = lane >> 2;
    const int t    = lane & 3;
    const int wm   = (wid / NWN) * WM;
    const int wn   = (wid % NWN) * WN;

    const int lk    = ((lane >> 3) & 1) * 8 + (lane & 7);
    const int lncol = ((lane >> 4) & 1) * 8;
    const uint32_t bhb = (uint32_t)__cvta_generic_to_shared(Bsh);
    const uint32_t blb = (uint32_t)__cvta_generic_to_shared(Bsl);

    const __half* Aph = Agh + (size_t)m0 * lda;
    const __half* Apl = Agl + (size_t)m0 * lda;
    const __half* Bph = Bgh + n0;
    const __half* Bpl = Bgl + n0;

    float acc[NMT][NNT][4];
    #pragma unroll
    for (int i = 0; i < NMT; i++)
        #pragma unroll
        for (int j = 0; j < NNT; j++)
            #pragma unroll
            for (int e = 0; e < 4; e++) acc[i][j][e] = 0.f;

    uint2 rAh[NA4], rAl[NA4], rBh[NB4], rBl[NB4];

    auto gload = [&](int k0) {
        #pragma unroll
        for (int e = 0; e < NA4; e++) {
            int f = tid + e * 256;
            size_t off = (size_t)(f >> 2) * lda + k0 + (f & 3) * 4;
            rAh[e] = *reinterpret_cast<const uint2*>(Aph + off);
            rAl[e] = *reinterpret_cast<const uint2*>(Apl + off);
        }
        #pragma unroll
        for (int e = 0; e < NB4; e++) {
            int f = tid + e * 256;
            size_t off = (size_t)(k0 + f / (BN / 4)) * ldb + (f % (BN / 4)) * 4;
            rBh[e] = *reinterpret_cast<const uint2*>(Bph + off);
            rBl[e] = *reinterpret_cast<const uint2*>(Bpl + off);
        }
    };

    auto sstore = [&]() {
        #pragma unroll
        for (int e = 0; e < NA4; e++) {
            int f = tid + e * 256; int m = f >> 2; int kq = (f & 3) * 4;
            *reinterpret_cast<uint2*>(Ash + m * AKP + kq) = rAh[e];
            *reinterpret_cast<uint2*>(Asl + m * AKP + kq) = rAl[e];
        }
        #pragma unroll
        for (int e = 0; e < NB4; e++) {
            int f = tid + e * 256; int kk = f / (BN / 4); int nq = (f % (BN / 4)) * 4;
            *reinterpret_cast<uint2*>(Bsh + kk * BNP + nq) = rBh[e];
            *reinterpret_cast<uint2*>(Bsl + kk * BNP + nq) = rBl[e];
        }
    };

    gload(0);
    sstore();
    __syncthreads();

    const int ntiles = K >> 4;
    for (int kt = 0; kt < ntiles; kt++) {
        const bool more = (kt + 1 < ntiles);
        if (more) gload((kt + 1) << 4);

        uint32_t ah[NMT][4], al[NMT][4];
        #pragma unroll
        for (int mt = 0; mt < NMT; mt++) {
            int r = wm + mt * 16 + g;
            const __half* Ar  = Ash + r * AKP;
            const __half* Ar8 = Ash + (r + 8) * AKP;
            ah[mt][0] = ldh2(Ar  + 2 * t);
            ah[mt][1] = ldh2(Ar8 + 2 * t);
            ah[mt][2] = ldh2(Ar  + 2 * t + 8);
            ah[mt][3] = ldh2(Ar8 + 2 * t + 8);
            const __half* Lr  = Asl + r * AKP;
            const __half* Lr8 = Asl + (r + 8) * AKP;
            al[mt][0] = ldh2(Lr  + 2 * t);
            al[mt][1] = ldh2(Lr8 + 2 * t);
            al[mt][2] = ldh2(Lr  + 2 * t + 8);
            al[mt][3] = ldh2(Lr8 + 2 * t + 8);
        }

        #pragma unroll
        for (int np = 0; np < NNT / 2; np++) {
            uint32_t off = (uint32_t)(lk * BNP + wn + np * 16 + lncol) * 2;
            uint32_t b0, b1, b2, b3, c0, c1, c2, c3;
            ldsm4t(b0, b1, b2, b3, bhb + off);
            ldsm4t(c0, c1, c2, c3, blb + off);
            #pragma unroll
            for (int mt = 0; mt < NMT; mt++) {
                mma_f16a(acc[mt][2 * np],     ah[mt], b0, b1);
                mma_f16a(acc[mt][2 * np],     al[mt], b0, b1);
                mma_f16a(acc[mt][2 * np],     ah[mt], c0, c1);
                mma_f16a(acc[mt][2 * np + 1], ah[mt], b2, b3);
                mma_f16a(acc[mt][2 * np + 1], al[mt], b2, b3);
                mma_f16a(acc[mt][2 * np + 1], ah[mt], c2, c3);
            }
        }
        __syncthreads();
        if (more) { sstore(); __syncthreads(); }
    }

    // Epilogue
    #pragma unroll
    for (int mt = 0; mt < NMT; mt++) {
        int r0 = m0 + wm + mt * 16 + g;
        #pragma unroll
        for (int nt = 0; nt < NNT; nt++) {
            int cc = n0 + wn + nt * 8 + t * 2;
            float v00 = acc[mt][nt][0], v01 = acc[mt][nt][1];
            float v10 = acc[mt][nt][2], v11 = acc[mt][nt][3];
            float b0 = bias[cc], b1 = bias[cc + 1];
            v00 += b0; v01 += b1; v10 += b0; v11 += b1;
            if (EPI == 1) {
                v00 = gelu_tanh(v00); v01 = gelu_tanh(v01);
                v10 = gelu_tanh(v10); v11 = gelu_tanh(v11);
            }
            if (EPI == 2) {
                v00 += R[(size_t)r0 * ldr + cc];
                v01 += R[(size_t)r0 * ldr + cc + 1];
                v10 += R[(size_t)(r0 + 8) * ldr + cc];
                v11 += R[(size_t)(r0 + 8) * ldr + cc + 1];
            }
            if (OUT == 0) {
                *reinterpret_cast<float2*>(&Cf[(size_t)r0 * ldc + cc]) = make_float2(v00, v01);
                *reinterpret_cast<float2*>(&Cf[(size_t)(r0 + 8) * ldc + cc]) = make_float2(v10, v11);
            } else if (OUT == 1) {
                __half h0, h1, h2, h3, l0, l1, l2, l3;
                h_split(v00, h0, l0); h_split(v01, h1, l1);
                h_split(v10, h2, l2); h_split(v11, h3, l3);
                *reinterpret_cast<uint32_t*>(&Ch[(size_t)r0 * ldc + cc])       = pack2(h0, h1);
                *reinterpret_cast<uint32_t*>(&Cl[(size_t)r0 * ldc + cc])       = pack2(l0, l1);
                *reinterpret_cast<uint32_t*>(&Ch[(size_t)(r0 + 8) * ldc + cc]) = pack2(h2, h3);
                *reinterpret_cast<uint32_t*>(&Cl[(size_t)(r0 + 8) * ldc + cc]) = pack2(l2, l3);
            } else {
                *reinterpret_cast<uint32_t*>(&Ch[(size_t)r0 * ldc + cc]) =
                    pack2(__float2half_rn(v00), __float2half_rn(v01));
                *reinterpret_cast<uint32_t*>(&Ch[(size_t)(r0 + 8) * ldc + cc]) =
                    pack2(__float2half_rn(v10), __float2half_rn(v11));
            }
        }
    }
}

// QKV fused (z: 0=q hi/lo, 1=k hi/lo, 2=v half)
__global__ __launch_bounds__(256, 1)
void qkv_kernel(const __half* __restrict__ hh, const __half* __restrict__ hl,
                const __half* __restrict__ wqh, const __half* __restrict__ wql,
                const __half* __restrict__ wkh, const __half* __restrict__ wkl,
                const __half* __restrict__ wvh, const __half* __restrict__ wvl,
                const float* __restrict__ bq, const float* __restrict__ bk,
                const float* __restrict__ bv,
                __half* qh, __half* ql, __half* kh, __half* kl, __half* vh)
{
    int z = blockIdx.z;
    int m0 = blockIdx.y * 128, n0 = blockIdx.x * 128;
    if (z == 0)
        gemm_core<128,128,64,32,0,1>(hh, hl, DD, wqh, wql, DD, bq, nullptr, 0,
                                     nullptr, qh, ql, DD, DD, m0, n0);
    else if (z == 1)
        gemm_core<128,128,64,32,0,1>(hh, hl, DD, wkh, wkl, DD, bk, nullptr, 0,
                                     nullptr, kh, kl, DD, DD, m0, n0);
    else
        gemm_core<128,128,64,32,0,2>(hh, hl, DD, wvh, wvl, DD, bv, nullptr, 0,
                                     nullptr, vh, nullptr, DD, DD, m0, n0);
}

template<int BM, int BN, int WM, int WN, int EPI, int OUT>
__global__ __launch_bounds__(256, (BN == 64) ? 2 : 1)
void mm_kernel(const __half* __restrict__ Ah, const __half* __restrict__ Al, int lda,
               const __half* __restrict__ Bh, const __half* __restrict__ Bl, int ldb,
               const float* __restrict__ bias,
               const float* __restrict__ R, int ldr,
               float* Cf, __half* Ch, __half* Cl, int ldc, int K)
{
    gemm_core<BM,BN,WM,WN,EPI,OUT>(Ah, Al, lda, Bh, Bl, ldb, bias, R, ldr,
                                   Cf, Ch, Cl, ldc, K,
                                   blockIdx.y * BM, blockIdx.x * BN);
}

// ---------------------------------------------------------------------------
// Fused flash attention (pre-split q/k, fp16 v). 128 thr = 4 warps.
// ---------------------------------------------------------------------------
__global__ __launch_bounds__(128, 2)
void flash_kernel(const __half* __restrict__ qh, const __half* __restrict__ ql,
                  const __half* __restrict__ kh, const __half* __restrict__ kl,
                  const __half* __restrict__ vh, const float* __restrict__ rel,
                  const int* __restrict__ rel_ids, const int* __restrict__ mask,
                  __half* __restrict__ ctxh, __half* __restrict__ ctxl)
{
    extern __shared__ __half smh[];
    __half*  Qh = smh;                 // [64][72]
    __half*  Ql = smh + 4608;
    __half*  Kh = smh + 9216;          // [128][72]
    __half*  Kl = smh + 18432;
    __half2* Vh = reinterpret_cast<__half2*>(smh + 27648);  // [64 jp][72 d]
    float*   rels = reinterpret_cast<float*>(smh + 36864);  // [64][33]

    const int tid  = threadIdx.x;
    const int lane = tid & 31;
    const int wid  = tid >> 5;
    const int g = lane >> 2, t = lane & 3;
    const int wm = wid << 4;

    const int i0 = blockIdx.x * 64;
    const int bh = blockIdx.y;
    const int b = bh / HH, hd = bh - b * HH;

    const __half* Qph = qh + (size_t)b * SS * DD + hd * DHH;
    const __half* Qpl = ql + (size_t)b * SS * DD + hd * DHH;
    const __half* Kph = kh + (size_t)b * SS * DD + hd * DHH;
    const __half* Kpl = kl + (size_t)b * SS * DD + hd * DHH;
    const __half* Vp  = vh + (size_t)b * SS * DD + hd * DHH;

    // Q tile -> smem
    {
        int row = tid & 63;
        int base = (tid >> 6) * 8;
        #pragma unroll
        for (int e = 0; e < 8; e++) {
            int dq = (base + e) * 4;
            size_t off = (size_t)(i0 + row) * DD + dq;
            *reinterpret_cast<uint2*>(Qh + row * 72 + dq) = *reinterpret_cast<const uint2*>(Qph + off);
            *reinterpret_cast<uint2*>(Ql + row * 72 + dq) = *reinterpret_cast<const uint2*>(Qpl + off);
        }
    }
    // rel rows -> rels[row][r]
    {
        const float* rp = rel + ((size_t)bh * SS + i0) * RELV;
        #pragma unroll
        for (int e = 0; e < 4; e++) {
            int f = tid + e * 128;
            float4 val = *reinterpret_cast<const float4*>(rp + f * 4);
            int row = f >> 3, r = (f & 7) * 4;
            rels[row * 33 + r + 0] = val.x;
            rels[row * 33 + r + 1] = val.y;
            rels[row * 33 + r + 2] = val.z;
            rels[row * 33 + r + 3] = val.w;
        }
    }
    __syncthreads();

    // Hoisted Q fragments
    uint32_t qfh[4][4], qfl[4][4];
    #pragma unroll
    for (int kc = 0; kc < 4; kc++) {
        int kb = kc * 16;
        const __half* r0h = Qh + (wm + g) * 72 + kb;
        const __half* r8h = r0h + 8 * 72;
        qfh[kc][0] = ldh2(r0h + 2 * t);
        qfh[kc][1] = ldh2(r8h + 2 * t);
        qfh[kc][2] = ldh2(r0h + 2 * t + 8);
        qfh[kc][3] = ldh2(r8h + 2 * t + 8);
        const __half* r0l = Ql + (wm + g) * 72 + kb;
        const __half* r8l = r0l + 8 * 72;
        qfl[kc][0] = ldh2(r0l + 2 * t);
        qfl[kc][1] = ldh2(r8l + 2 * t);
        qfl[kc][2] = ldh2(r0l + 2 * t + 8);
        qfl[kc][3] = ldh2(r8l + 2 * t + 8);
    }

    float m0r = -1e30f, m1r = -1e30f;
    float l0r = 0.f, l1r = 0.f;
    float oacc[8][4];
    #pragma unroll
    for (int nt = 0; nt < 8; nt++) {
        oacc[nt][0] = 0.f; oacc[nt][1] = 0.f; oacc[nt][2] = 0.f; oacc[nt][3] = 0.f;
    }

    const int ig0 = i0 + wm + g;
    const int ig1 = ig0 + 8;
    const int* rid0 = rel_ids + ((size_t)b * SS + ig0) * SS + 2 * t;
    const int* rid1 = rel_ids + ((size_t)b * SS + ig1) * SS + 2 * t;
    const int* mk0  = mask    + ((size_t)b * SS + ig0) * SS + 2 * t;
    const int* mk1  = mask    + ((size_t)b * SS + ig1) * SS + 2 * t;
    const float* rl0 = rels + (wm + g) * 33;
    const float* rl1 = rl0 + 8 * 33;

    for (int jt = 0; jt < 8; jt++) {
        const int j0 = jt * 128;
        __syncthreads();
        // K tile
        #pragma unroll
        for (int e = 0; e < 16; e++) {
            int dq = e * 4;
            size_t off = (size_t)(j0 + tid) * DD + dq;
            *reinterpret_cast<uint2*>(Kh + tid * 72 + dq) = *reinterpret_cast<const uint2*>(Kph + off);
            *reinterpret_cast<uint2*>(Kl + tid * 72 + dq) = *reinterpret_cast<const uint2*>(Kpl + off);
        }
        // V tile: interleave row pairs
        #pragma unroll
        for (int e = 0; e < 8; e++) {
            int f = tid + e * 128;
            int jp = f >> 4, dq = (f & 15) * 4;
            uint2 a = *reinterpret_cast<const uint2*>(Vp + (size_t)(j0 + 2 * jp) * DD + dq);
            uint2 c = *reinterpret_cast<const uint2*>(Vp + (size_t)(j0 + 2 * jp + 1) * DD + dq);
            __half2 ax = *reinterpret_cast<__half2*>(&a.x);
            __half2 ay = *reinterpret_cast<__half2*>(&a.y);
            __half2 cx = *reinterpret_cast<__half2*>(&c.x);
            __half2 cy = *reinterpret_cast<__half2*>(&c.y);
            __half2* dst = Vh + jp * 72 + dq;
            dst[0] = __lows2half2 (ax, cx);
            dst[1] = __highs2half2(ax, cx);
            dst[2] = __lows2half2 (ay, cy);
            dst[3] = __highs2half2(ay, cy);
        }
        __syncthreads();

        // S = Q K^T (fp16x3)
        float sacc[16][4];
        #pragma unroll
        for (int nt = 0; nt < 16; nt++) {
            sacc[nt][0] = 0.f; sacc[nt][1] = 0.f; sacc[nt][2] = 0.f; sacc[nt][3] = 0.f;
        }
        #pragma unroll
        for (int kc = 0; kc < 4; kc++) {
            int kb = kc * 16;
            #pragma unroll
            for (int nt = 0; nt < 16; nt++) {
                const __half* nbh = Kh + (nt * 8 + g) * 72 + kb;
                const __half* nbl = Kl + (nt * 8 + g) * 72 + kb;
                uint32_t b0 = ldh2(nbh + 2 * t);
                uint32_t b1 = ldh2(nbh + 2 * t + 8);
                uint32_t c0 = ldh2(nbl + 2 * t);
                uint32_t c1 = ldh2(nbl + 2 * t + 8);
                mma_f16a(sacc[nt], qfh[kc], b0, b1);
                mma_f16a(sacc[nt], qfl[kc], b0, b1);
                mma_f16a(sacc[nt], qfh[kc], c0, c1);
            }
        }

        // rel gather + mask + scale
        float mx0 = -1e30f, mx1 = -1e30f;
        #pragma unroll
        for (int nt = 0; nt < 16; nt++) {
            int jo = j0 + nt * 8;
            int2 i0v = *reinterpret_cast<const int2*>(rid0 + jo);
            int2 i1v = *reinterpret_cast<const int2*>(rid1 + jo);
            int2 m0v = *reinterpret_cast<const int2*>(mk0 + jo);
            int2 m1v = *reinterpret_cast<const int2*>(mk1 + jo);
            sacc[nt][0] = (sacc[nt][0] + rl0[i0v.x]) * 0.125f + (1.f - (float)m0v.x) * -10000.f;
            sacc[nt][1] = (sacc[nt][1] + rl0[i0v.y]) * 0.125f + (1.f - (float)m0v.y) * -10000.f;
            sacc[nt][2] = (sacc[nt][2] + rl1[i1v.x]) * 0.125f + (1.f - (float)m1v.x) * -10000.f;
            sacc[nt][3] = (sacc[nt][3] + rl1[i1v.y]) * 0.125f + (1.f - (float)m1v.y) * -10000.f;
            mx0 = fmaxf(mx0, fmaxf(sacc[nt][0], sacc[nt][1]));
            mx1 = fmaxf(mx1, fmaxf(sacc[nt][2], sacc[nt][3]));
        }
        mx0 = fmaxf(mx0, __shfl_xor_sync(0xffffffffu, mx0, 1));
        mx0 = fmaxf(mx0, __shfl_xor_sync(0xffffffffu, mx0, 2));
        mx1 = fmaxf(mx1, __shfl_xor_sync(0xffffffffu, mx1, 1));
        mx1 = fmaxf(mx1, __shfl_xor_sync(0xffffffffu, mx1, 2));
        float mn0 = fmaxf(m0r, mx0), mn1 = fmaxf(m1r, mx1);
        float al0 = __expf(m0r - mn0), al1 = __expf(m1r - mn1);
        m0r = mn0; m1r = mn1;

        uint32_t ph[16][2];
        float s0 = 0.f, s1 = 0.f;
        #pragma unroll
        for (int nt = 0; nt < 16; nt++) {
            float p0 = __expf(sacc[nt][0] - mn0);
            float p1 = __expf(sacc[nt][1] - mn0);
            float p2 = __expf(sacc[nt][2] - mn1);
            float p3 = __expf(sacc[nt][3] - mn1);
            s0 += p0 + p1; s1 += p2 + p3;
            __half2 h01 = __floats2half2_rn(p0, p1);
            __half2 h23 = __floats2half2_rn(p2, p3);
            ph[nt][0] = *reinterpret_cast<uint32_t*>(&h01);
            ph[nt][1] = *reinterpret_cast<uint32_t*>(&h23);
        }
        l0r = l0r * al0 + s0;
        l1r = l1r * al1 + s1;
        #pragma unroll
        for (int nt = 0; nt < 8; nt++) {
            oacc[nt][0] *= al0; oacc[nt][1] *= al0;
            oacc[nt][2] *= al1; oacc[nt][3] *= al1;
        }
        #pragma unroll
        for (int kc = 0; kc < 8; kc++) {
            uint32_t a0 = ph[2 * kc][0],     a1 = ph[2 * kc][1];
            uint32_t a2 = ph[2 * kc + 1][0], a3 = ph[2 * kc + 1][1];
            #pragma unroll
            for (int nt = 0; nt < 8; nt++) {
                uint32_t b0 = *reinterpret_cast<const uint32_t*>(&Vh[(kc * 8 + t) * 72 + nt * 8 + g]);
                uint32_t b1 = *reinterpret_cast<const uint32_t*>(&Vh[(kc * 8 + t + 4) * 72 + nt * 8 + g]);
                mma_f16(oacc[nt], a0, a1, a2, a3, b0, b1);
            }
        }
    }

    l0r += __shfl_xor_sync(0xffffffffu, l0r, 1);
    l0r += __shfl_xor_sync(0xffffffffu, l0r, 2);
    l1r += __shfl_xor_sync(0xffffffffu, l1r, 1);
    l1r += __shfl_xor_sync(0xffffffffu, l1r, 2);
    float inv0 = 1.f / l0r, inv1 = 1.f / l1r;
    size_t o0 = ((size_t)b * SS + ig0) * DD + hd * DHH + 2 * t;
    size_t o1 = ((size_t)b * SS + ig1) * DD + hd * DHH + 2 * t;
    #pragma unroll
    for (int nt = 0; nt < 8; nt++) {
        float v0 = oacc[nt][0] * inv0, v1 = oacc[nt][1] * inv0;
        float v2 = oacc[nt][2] * inv1, v3 = oacc[nt][3] * inv1;
        __half h0, h1, h2, h3, l0, l1, l2, l3;
        h_split(v0, h0, l0); h_split(v1, h1, l1);
        h_split(v2, h2, l2); h_split(v3, h3, l3);
        *reinterpret_cast<uint32_t*>(&ctxh[o0 + nt * 8]) = pack2(h0, h1);
        *reinterpret_cast<uint32_t*>(&ctxl[o0 + nt * 8]) = pack2(l0, l1);
        *reinterpret_cast<uint32_t*>(&ctxh[o1 + nt * 8]) = pack2(h2, h3);
        *reinterpret_cast<uint32_t*>(&ctxl[o1 + nt * 8]) = pack2(l2, l3);
    }
}

// ---------------------------------------------------------------------------
// Block reduction (256 threads)
// ---------------------------------------------------------------------------
__device__ __forceinline__ float bsum256(float v) {
    __shared__ float sm[8];
    #pragma unroll
    for (int o = 16; o; o >>= 1) v += __shfl_xor_sync(0xffffffffu, v, o);
    if ((threadIdx.x & 31) == 0) sm[threadIdx.x >> 5] = v;
    __syncthreads();
    float r = 0.f;
    #pragma unroll
    for (int i = 0; i < 8; i++) r += sm[i];
    __syncthreads();
    return r;
}

// ---------------------------------------------------------------------------
// Embedding
// ---------------------------------------------------------------------------
__global__ void embed_kernel(const int* __restrict__ token_ids,
                             const int* __restrict__ segment_ids,
                             const int* __restrict__ position_ids,
                             const int* __restrict__ question_mask,
                             const float* __restrict__ tok_emb,
                             const float* __restrict__ seg_emb,
                             float* __restrict__ x)
{
    int row = blockIdx.x;
    int tok = token_ids[row];
    int seg = segment_ids[row];
    int qmi = question_mask[row];
    float qm = (float)qmi;
    int pos = position_ids[row] * qmi;
    float fpos = (float)pos;

    const float* te = tok_emb + (size_t)tok * DD;
    const float* se = seg_emb + (size_t)seg * DD;
    float* xr = x + (size_t)row * DD;

    for (int i = threadIdx.x; i < DD; i += 256) {
        float ex  = (float)(2 * (i >> 1)) * (1.0f / (float)DD);
        float inv = __powf(10000.0f, -ex);
        float ang = fpos * inv;
        float pe  = (i & 1) ? cosf(ang) : sinf(ang);
        xr[i] = te[i] + se[i] + pe * qm;
    }
}

// ---------------------------------------------------------------------------
// LayerNorm -> hi/lo half planes
// ---------------------------------------------------------------------------
__global__ void ln_kernel(const float* __restrict__ x,
                          const float* __restrict__ gamma,
                          const float* __restrict__ beta,
                          __half* __restrict__ oh, __half* __restrict__ ol)
{
    int row = blockIdx.x;
    const float* xr = x + (size_t)row * DD;
    int t = threadIdx.x;
    float v0 = xr[t], v1 = xr[t + 256], v2 = xr[t + 512];

    float s = bsum256(v0 + v1 + v2);
    float mu = s * (1.0f / (float)DD);
    float d0 = v0 - mu, d1 = v1 - mu, d2 = v2 - mu;
    float s2 = bsum256(d0*d0 + d1*d1 + d2*d2);
    float rstd = rsqrtf(s2 * (1.0f / (float)DD) + 1e-12f);

    float r0 = d0 * rstd * gamma[t]       + beta[t];
    float r1 = d1 * rstd * gamma[t + 256] + beta[t + 256];
    float r2 = d2 * rstd * gamma[t + 512] + beta[t + 512];
    __half h0, h1, h2, l0, l1, l2;
    h_split(r0, h0, l0); h_split(r1, h1, l1); h_split(r2, h2, l2);
    size_t base = (size_t)row * DD;
    oh[base + t]       = h0; ol[base + t]       = l0;
    oh[base + t + 256] = h1; ol[base + t + 256] = l1;
    oh[base + t + 512] = h2; ol[base + t + 512] = l2;
}

// ---------------------------------------------------------------------------
// Relative bias: rel[bh,i,r] = sum_d q[b,i,h,d] * rel_emb[r,h,d]
// ---------------------------------------------------------------------------
__global__ void rel_kernel(const __half* __restrict__ qh,
                           const __half* __restrict__ ql,
                           const float* __restrict__ relw,
                           float* __restrict__ rel)
{
    int bh = blockIdx.y;
    int b = bh / HH, h = bh % HH;
    int i0 = blockIdx.x * 8;

    __shared__ float Rs[RELV][65];
    __shared__ float Qs[8][DHH];

    int tid = threadIdx.x;
    #pragma unroll
    for (int e = 0; e < 8; e++) {
        int idx = tid + e * 256;
        int r = idx >> 6, d = idx & 63;
        Rs[r][d] = relw[((size_t)r * HH + h) * DHH + d];
    }
    #pragma unroll
    for (int e = 0; e < 2; e++) {
        int idx = tid + e * 256;
        int ii = idx >> 6, d = idx & 63;
        size_t off = (size_t)b * SS * DD + (size_t)(i0 + ii) * DD + h * DHH + d;
        Qs[ii][d] = __half2float(qh[off]) + __half2float(ql[off]);
    }
    __syncthreads();

    int r = tid & 31, iy = tid >> 5;
    float s = 0.f;
    #pragma unroll
    for (int d = 0; d < 64; d++) s += Qs[iy][d] * Rs[r][d];
    rel[((size_t)bh * SS + i0 + iy) * RELV + r] = s;
}

// ---------------------------------------------------------------------------
// Launch
// ---------------------------------------------------------------------------
extern "C" void kernel_launch(void* const* d_in, const int* in_sizes, int n_in,
                              void* d_out, int out_size)
{
    const int* token_ids     = (const int*)d_in[0];
    const int* segment_ids   = (const int*)d_in[1];
    const int* position_ids  = (const int*)d_in[2];
    const int* question_mask = (const int*)d_in[3];
    const int* attention_mask= (const int*)d_in[4];
    const int* rel_ids       = (const int*)d_in[5];
    const float* tok_emb = (const float*)d_in[6];
    const float* seg_emb = (const float*)d_in[7];
    const float* ln1_g = (const float*)d_in[8];
    const float* ln1_b = (const float*)d_in[9];
    const float* ln2_g = (const float*)d_in[10];
    const float* ln2_b = (const float*)d_in[11];
    const float* wq = (const float*)d_in[12];
    const float* bq = (const float*)d_in[13];
    const float* wk = (const float*)d_in[14];
    const float* bk = (const float*)d_in[15];
    const float* wv = (const float*)d_in[16];
    const float* bv = (const float*)d_in[17];
    const float* wo = (const float*)d_in[18];
    const float* bo = (const float*)d_in[19];
    const float* rel_emb = (const float*)d_in[20];
    const float* w1 = (const float*)d_in[21];
    const float* b1 = (const float*)d_in[22];
    const float* w2 = (const float*)d_in[23];
    const float* b2 = (const float*)d_in[24];

    float *x, *rl;
    __half *hh, *hl, *qh, *ql, *kh, *kl, *vh, *ch, *cl, *ffh, *ffl, *wh, *wl;
    cudaGetSymbolAddress((void**)&x,   g_x);
    cudaGetSymbolAddress((void**)&rl,  g_rel);
    cudaGetSymbolAddress((void**)&hh,  g_hh);
    cudaGetSymbolAddress((void**)&hl,  g_hl);
    cudaGetSymbolAddress((void**)&qh,  g_qh);
    cudaGetSymbolAddress((void**)&ql,  g_ql);
    cudaGetSymbolAddress((void**)&kh,  g_kh);
    cudaGetSymbolAddress((void**)&kl,  g_kl);
    cudaGetSymbolAddress((void**)&vh,  g_vh);
    cudaGetSymbolAddress((void**)&ch,  g_ch);
    cudaGetSymbolAddress((void**)&cl,  g_cl);
    cudaGetSymbolAddress((void**)&ffh, g_ffh);
    cudaGetSymbolAddress((void**)&ffl, g_ffl);
    cudaGetSymbolAddress((void**)&wh,  g_wh);
    cudaGetSymbolAddress((void**)&wl,  g_wl);

    const int FLASH_SMEM = 82176;
    cudaFuncSetAttribute(flash_kernel,
                         cudaFuncAttributeMaxDynamicSharedMemorySize, FLASH_SMEM);

    // Pre-split all weights into hi/lo half planes
    {
        int n4;
        n4 = WDD / 4;
        split_kernel<<<(n4 + 255) / 256, 256>>>(wq, wh + OFF_WQ, wl + OFF_WQ, n4);
        split_kernel<<<(n4 + 255) / 256, 256>>>(wk, wh + OFF_WK, wl + OFF_WK, n4);
        split_kernel<<<(n4 + 255) / 256, 256>>>(wv, wh + OFF_WV, wl + OFF_WV, n4);
        split_kernel<<<(n4 + 255) / 256, 256>>>(wo, wh + OFF_WO, wl + OFF_WO, n4);
        n4 = WDF / 4;
        split_kernel<<<(n4 + 255) / 256, 256>>>(w1, wh + OFF_W1, wl + OFF_W1, n4);
        split_kernel<<<(n4 + 255) / 256, 256>>>(w2, wh + OFF_W2, wl + OFF_W2, n4);
    }

    embed_kernel<<<NROW, 256>>>(token_ids, segment_ids, position_ids,
                                question_mask, tok_emb, seg_emb, x);

    for (int l = 0; l < LL; l++) {
        size_t odd = (size_t)l * DD * DD;
        size_t odf = (size_t)l * DD * FF;

        // --- attention block ---
        ln_kernel<<<NROW, 256>>>(x, ln1_g + l * DD, ln1_b + l * DD, hh, hl);

        qkv_kernel<<<dim3(DD / 128, NROW / 128, 3), 256>>>(
            hh, hl,
            wh + OFF_WQ + odd, wl + OFF_WQ + odd,
            wh + OFF_WK + odd, wl + OFF_WK + odd,
            wh + OFF_WV + odd, wl + OFF_WV + odd,
            bq + l * DD, bk + l * DD, bv + l * DD,
            qh, ql, kh, kl, vh);

        rel_kernel<<<dim3(SS / 8, BB * HH), 256>>>(
            qh, ql, rel_emb + (size_t)l * RELV * HH * DHH, rl);

        flash_kernel<<<dim3(SS / 64, BB * HH), 128, FLASH_SMEM>>>(
            qh, ql, kh, kl, vh, rl, rel_ids, attention_mask, ch, cl);

        mm_kernel<128,64,32,32,2,0><<<dim3(DD / 64, NROW / 128), 256>>>(
            ch, cl, DD, wh + OFF_WO + odd, wl + OFF_WO + odd, DD,
            bo + l * DD, x, DD, x, nullptr, nullptr, DD, DD);

        // --- FFN block ---
        ln_kernel<<<NROW, 256>>>(x, ln2_g + l * DD, ln2_b + l * DD, hh, hl);
        mm_kernel<128,128,64,32,1,1><<<dim3(FF / 128, NROW / 128), 256>>>(
            hh, hl, DD, wh + OFF_W1 + odf, wl + OFF_W1 + odf, FF,
            b1 + l * FF, nullptr, 0, nullptr, ffh, ffl, FF, DD);

        float* outp = (l == LL - 1) ? (float*)d_out : x;
        mm_kernel<128,64,32,32,2,0><<<dim3(DD / 64, NROW / 128), 256>>>(
            ffh, ffl, FF, wh + OFF_W2 + odf, wl + OFF_W2 + odf, DD,
            b2 + l * DD, x, DD, outp, nullptr, nullptr, DD, FF);
    }
}

// round 6
// speedup vs baseline: 1.0669x; 1.0669x over previous
#include <cuda_runtime.h>
#include <cuda_fp16.h>
#include <math.h>
#include <stdint.h>

// Problem constants
#define BB   2
#define SS   1024
#define DD   768
#define HH   12
#define DHH  64
#define LL   6
#define FF   3072
#define RELV 32
#define NROW (BB*SS)

// Weight-plane offsets (in elements)
#define WDD  (LL*DD*DD)
#define WDF  (LL*DD*FF)
#define OFF_WQ 0
#define OFF_WK (WDD)
#define OFF_WV (2*WDD)
#define OFF_WO (3*WDD)
#define OFF_W1 (4*WDD)
#define OFF_W2 (4*WDD + WDF)
#define WTOT   (4*WDD + 2*WDF)

// ---------------------------------------------------------------------------
// Scratch (device globals)
// ---------------------------------------------------------------------------
__device__ float g_x  [NROW*DD];
__device__ float g_rel[(size_t)BB*HH*SS*RELV];
__device__ __align__(16) __half g_hh [NROW*DD];
__device__ __align__(16) __half g_hl [NROW*DD];
__device__ __align__(16) __half g_qh [NROW*DD];
__device__ __align__(16) __half g_ql [NROW*DD];
__device__ __align__(16) __half g_kh [NROW*DD];
__device__ __align__(16) __half g_kl [NROW*DD];
__device__ __align__(16) __half g_vh [NROW*DD];
__device__ __align__(16) __half g_ch [NROW*DD];
__device__ __align__(16) __half g_cl [NROW*DD];
__device__ __align__(16) __half g_ffh[(size_t)NROW*FF];
__device__ __align__(16) __half g_ffl[(size_t)NROW*FF];
__device__ __align__(16) __half g_wh [WTOT];
__device__ __align__(16) __half g_wl [WTOT];

// ---------------------------------------------------------------------------
// helpers
// ---------------------------------------------------------------------------
__device__ __forceinline__ void h_split(float v, __half& hi, __half& lo) {
    hi = __float2half_rn(v);
    lo = __float2half_rn(v - __half2float(hi));
}

__device__ __forceinline__ uint32_t pack2(__half a, __half b) {
    __half2 t = __halves2half2(a, b);
    return *reinterpret_cast<uint32_t*>(&t);
}

__device__ __forceinline__ uint32_t ldh2(const __half* p) {
    return *reinterpret_cast<const uint32_t*>(p);
}

__device__ __forceinline__ void mma_f16(float c[4], uint32_t a0, uint32_t a1,
                                        uint32_t a2, uint32_t a3,
                                        uint32_t b0, uint32_t b1) {
    asm volatile(
        "mma.sync.aligned.m16n8k16.row.col.f32.f16.f16.f32 "
        "{%0,%1,%2,%3},{%4,%5,%6,%7},{%8,%9},{%0,%1,%2,%3};"
        : "+f"(c[0]), "+f"(c[1]), "+f"(c[2]), "+f"(c[3])
        : "r"(a0), "r"(a1), "r"(a2), "r"(a3), "r"(b0), "r"(b1));
}

__device__ __forceinline__ void mma_f16a(float c[4], const uint32_t a[4],
                                         uint32_t b0, uint32_t b1) {
    mma_f16(c, a[0], a[1], a[2], a[3], b0, b1);
}

__device__ __forceinline__ void ldsm4t(uint32_t& r0, uint32_t& r1,
                                       uint32_t& r2, uint32_t& r3, uint32_t a) {
    asm volatile("ldmatrix.sync.aligned.m8n8.x4.trans.shared.b16 {%0,%1,%2,%3}, [%4];"
                 : "=r"(r0), "=r"(r1), "=r"(r2), "=r"(r3) : "r"(a));
}

__device__ __forceinline__ float gelu_tanh(float v) {
    float u = 0.7978845608028654f * (v + 0.044715f * v * v * v);
    return 0.5f * v * (1.0f + tanhf(u));
}

// ---------------------------------------------------------------------------
// split kernel: fp32 -> (hi,lo) half planes
// ---------------------------------------------------------------------------
__global__ void split_kernel(const float* __restrict__ s,
                             __half* __restrict__ hi, __half* __restrict__ lo,
                             int n4)
{
    int i = blockIdx.x * 256 + threadIdx.x;
    if (i >= n4) return;
    float4 v = reinterpret_cast<const float4*>(s)[i];
    __half h0, h1, h2, h3, l0, l1, l2, l3;
    h_split(v.x, h0, l0); h_split(v.y, h1, l1);
    h_split(v.z, h2, l2); h_split(v.w, h3, l3);
    uint2 ph, pl;
    ph.x = pack2(h0, h1); ph.y = pack2(h2, h3);
    pl.x = pack2(l0, l1); pl.y = pack2(l2, l3);
    reinterpret_cast<uint2*>(hi)[i] = ph;
    reinterpret_cast<uint2*>(lo)[i] = pl;
}

// ---------------------------------------------------------------------------
// GEMM core, pre-split halves. C = A@B + epilogue.
// EPI: 0=bias, 1=bias+gelu, 2=bias+residual
// OUT: 0=fp32, 1=hi/lo halves, 2=single half
// ---------------------------------------------------------------------------
template<int BM, int BN, int WM, int WN, int EPI, int OUT>
__device__ __forceinline__ void gemm_core(
    const __half* __restrict__ Agh, const __half* __restrict__ Agl, int lda,
    const __half* __restrict__ Bgh, const __half* __restrict__ Bgl, int ldb,
    const float* __restrict__ bias,
    const float* __restrict__ R, int ldr,
    float* __restrict__ Cf, __half* __restrict__ Ch, __half* __restrict__ Cl,
    int ldc, int K, int m0, int n0)
{
    constexpr int NWN = BN / WN;
    constexpr int NMT = WM / 16;
    constexpr int NNT = WN / 8;
    constexpr int NA4 = (BM * 16) / 1024;
    constexpr int NB4 = (BN * 16) / 1024;
    constexpr int AKP = 24;
    constexpr int BNP = BN + 8;
    constexpr int ASZ = BM * AKP;
    constexpr int BSZ = 16 * BNP;

    __shared__ __align__(16) __half sh[2 * ASZ + 2 * BSZ];
    __half* Ash = sh;
    __half* Asl = sh + ASZ;
    __half* Bsh = sh + 2 * ASZ;
    __half* Bsl = sh + 2 * ASZ + BSZ;

    const int tid  = threadIdx.x;
    const int lane = tid & 31;
    const int wid  = tid >> 5;
    const int g    = lane >> 2;
    const int t    = lane & 3;
    const int wm   = (wid / NWN) * WM;
    const int wn   = (wid % NWN) * WN;

    const int lk    = ((lane >> 3) & 1) * 8 + (lane & 7);
    const int lncol = ((lane >> 4) & 1) * 8;
    const uint32_t bhb = (uint32_t)__cvta_generic_to_shared(Bsh);
    const uint32_t blb = (uint32_t)__cvta_generic_to_shared(Bsl);

    const __half* Aph = Agh + (size_t)m0 * lda;
    const __half* Apl = Agl + (size_t)m0 * lda;
    const __half* Bph = Bgh + n0;
    const __half* Bpl = Bgl + n0;

    float acc[NMT][NNT][4];
    #pragma unroll
    for (int i = 0; i < NMT; i++)
        #pragma unroll
        for (int j = 0; j < NNT; j++)
            #pragma unroll
            for (int e = 0; e < 4; e++) acc[i][j][e] = 0.f;

    uint2 rAh[NA4], rAl[NA4], rBh[NB4], rBl[NB4];

    auto gload = [&](int k0) {
        #pragma unroll
        for (int e = 0; e < NA4; e++) {
            int f = tid + e * 256;
            size_t off = (size_t)(f >> 2) * lda + k0 + (f & 3) * 4;
            rAh[e] = *reinterpret_cast<const uint2*>(Aph + off);
            rAl[e] = *reinterpret_cast<const uint2*>(Apl + off);
        }
        #pragma unroll
        for (int e = 0; e < NB4; e++) {
            int f = tid + e * 256;
            size_t off = (size_t)(k0 + f / (BN / 4)) * ldb + (f % (BN / 4)) * 4;
            rBh[e] = *reinterpret_cast<const uint2*>(Bph + off);
            rBl[e] = *reinterpret_cast<const uint2*>(Bpl + off);
        }
    };

    auto sstore = [&]() {
        #pragma unroll
        for (int e = 0; e < NA4; e++) {
            int f = tid + e * 256; int m = f >> 2; int kq = (f & 3) * 4;
            *reinterpret_cast<uint2*>(Ash + m * AKP + kq) = rAh[e];
            *reinterpret_cast<uint2*>(Asl + m * AKP + kq) = rAl[e];
        }
        #pragma unroll
        for (int e = 0; e < NB4; e++) {
            int f = tid + e * 256; int kk = f / (BN / 4); int nq = (f % (BN / 4)) * 4;
            *reinterpret_cast<uint2*>(Bsh + kk * BNP + nq) = rBh[e];
            *reinterpret_cast<uint2*>(Bsl + kk * BNP + nq) = rBl[e];
        }
    };

    gload(0);
    sstore();
    __syncthreads();

    const int ntiles = K >> 4;
    for (int kt = 0; kt < ntiles; kt++) {
        const bool more = (kt + 1 < ntiles);
        if (more) gload((kt + 1) << 4);

        uint32_t ah[NMT][4], al[NMT][4];
        #pragma unroll
        for (int mt = 0; mt < NMT; mt++) {
            int r = wm + mt * 16 + g;
            const __half* Ar  = Ash + r * AKP;
            const __half* Ar8 = Ash + (r + 8) * AKP;
            ah[mt][0] = ldh2(Ar  + 2 * t);
            ah[mt][1] = ldh2(Ar8 + 2 * t);
            ah[mt][2] = ldh2(Ar  + 2 * t + 8);
            ah[mt][3] = ldh2(Ar8 + 2 * t + 8);
            const __half* Lr  = Asl + r * AKP;
            const __half* Lr8 = Asl + (r + 8) * AKP;
            al[mt][0] = ldh2(Lr  + 2 * t);
            al[mt][1] = ldh2(Lr8 + 2 * t);
            al[mt][2] = ldh2(Lr  + 2 * t + 8);
            al[mt][3] = ldh2(Lr8 + 2 * t + 8);
        }

        #pragma unroll
        for (int np = 0; np < NNT / 2; np++) {
            uint32_t off = (uint32_t)(lk * BNP + wn + np * 16 + lncol) * 2;
            uint32_t b0, b1, b2, b3, c0, c1, c2, c3;
            ldsm4t(b0, b1, b2, b3, bhb + off);
            ldsm4t(c0, c1, c2, c3, blb + off);
            #pragma unroll
            for (int mt = 0; mt < NMT; mt++) {
                mma_f16a(acc[mt][2 * np],     ah[mt], b0, b1);
                mma_f16a(acc[mt][2 * np],     al[mt], b0, b1);
                mma_f16a(acc[mt][2 * np],     ah[mt], c0, c1);
                mma_f16a(acc[mt][2 * np + 1], ah[mt], b2, b3);
                mma_f16a(acc[mt][2 * np + 1], al[mt], b2, b3);
                mma_f16a(acc[mt][2 * np + 1], ah[mt], c2, c3);
            }
        }
        __syncthreads();
        if (more) { sstore(); __syncthreads(); }
    }

    // Epilogue
    #pragma unroll
    for (int mt = 0; mt < NMT; mt++) {
        int r0 = m0 + wm + mt * 16 + g;
        #pragma unroll
        for (int nt = 0; nt < NNT; nt++) {
            int cc = n0 + wn + nt * 8 + t * 2;
            float v00 = acc[mt][nt][0], v01 = acc[mt][nt][1];
            float v10 = acc[mt][nt][2], v11 = acc[mt][nt][3];
            float b0 = bias[cc], b1 = bias[cc + 1];
            v00 += b0; v01 += b1; v10 += b0; v11 += b1;
            if (EPI == 1) {
                v00 = gelu_tanh(v00); v01 = gelu_tanh(v01);
                v10 = gelu_tanh(v10); v11 = gelu_tanh(v11);
            }
            if (EPI == 2) {
                v00 += R[(size_t)r0 * ldr + cc];
                v01 += R[(size_t)r0 * ldr + cc + 1];
                v10 += R[(size_t)(r0 + 8) * ldr + cc];
                v11 += R[(size_t)(r0 + 8) * ldr + cc + 1];
            }
            if (OUT == 0) {
                *reinterpret_cast<float2*>(&Cf[(size_t)r0 * ldc + cc]) = make_float2(v00, v01);
                *reinterpret_cast<float2*>(&Cf[(size_t)(r0 + 8) * ldc + cc]) = make_float2(v10, v11);
            } else if (OUT == 1) {
                __half h0, h1, h2, h3, l0, l1, l2, l3;
                h_split(v00, h0, l0); h_split(v01, h1, l1);
                h_split(v10, h2, l2); h_split(v11, h3, l3);
                *reinterpret_cast<uint32_t*>(&Ch[(size_t)r0 * ldc + cc])       = pack2(h0, h1);
                *reinterpret_cast<uint32_t*>(&Cl[(size_t)r0 * ldc + cc])       = pack2(l0, l1);
                *reinterpret_cast<uint32_t*>(&Ch[(size_t)(r0 + 8) * ldc + cc]) = pack2(h2, h3);
                *reinterpret_cast<uint32_t*>(&Cl[(size_t)(r0 + 8) * ldc + cc]) = pack2(l2, l3);
            } else {
                *reinterpret_cast<uint32_t*>(&Ch[(size_t)r0 * ldc + cc]) =
                    pack2(__float2half_rn(v00), __float2half_rn(v01));
                *reinterpret_cast<uint32_t*>(&Ch[(size_t)(r0 + 8) * ldc + cc]) =
                    pack2(__float2half_rn(v10), __float2half_rn(v11));
            }
        }
    }
}

// QKV fused (z: 0=q hi/lo, 1=k hi/lo, 2=v half)
__global__ __launch_bounds__(256, 1)
void qkv_kernel(const __half* __restrict__ hh, const __half* __restrict__ hl,
                const __half* __restrict__ wqh, const __half* __restrict__ wql,
                const __half* __restrict__ wkh, const __half* __restrict__ wkl,
                const __half* __restrict__ wvh, const __half* __restrict__ wvl,
                const float* __restrict__ bq, const float* __restrict__ bk,
                const float* __restrict__ bv,
                __half* qh, __half* ql, __half* kh, __half* kl, __half* vh)
{
    int z = blockIdx.z;
    int m0 = blockIdx.y * 128, n0 = blockIdx.x * 128;
    if (z == 0)
        gemm_core<128,128,64,32,0,1>(hh, hl, DD, wqh, wql, DD, bq, nullptr, 0,
                                     nullptr, qh, ql, DD, DD, m0, n0);
    else if (z == 1)
        gemm_core<128,128,64,32,0,1>(hh, hl, DD, wkh, wkl, DD, bk, nullptr, 0,
                                     nullptr, kh, kl, DD, DD, m0, n0);
    else
        gemm_core<128,128,64,32,0,2>(hh, hl, DD, wvh, wvl, DD, bv, nullptr, 0,
                                     nullptr, vh, nullptr, DD, DD, m0, n0);
}

template<int BM, int BN, int WM, int WN, int EPI, int OUT>
__global__ __launch_bounds__(256, (BM == 64) ? 2 : 1)
void mm_kernel(const __half* __restrict__ Ah, const __half* __restrict__ Al, int lda,
               const __half* __restrict__ Bh, const __half* __restrict__ Bl, int ldb,
               const float* __restrict__ bias,
               const float* __restrict__ R, int ldr,
               float* Cf, __half* Ch, __half* Cl, int ldc, int K)
{
    gemm_core<BM,BN,WM,WN,EPI,OUT>(Ah, Al, lda, Bh, Bl, ldb, bias, R, ldr,
                                   Cf, Ch, Cl, ldc, K,
                                   blockIdx.y * BM, blockIdx.x * BN);
}

// ---------------------------------------------------------------------------
// Fused flash attention (pre-split q/k, fp16 v). 128 thr = 4 warps.
// ---------------------------------------------------------------------------
__global__ __launch_bounds__(128, 2)
void flash_kernel(const __half* __restrict__ qh, const __half* __restrict__ ql,
                  const __half* __restrict__ kh, const __half* __restrict__ kl,
                  const __half* __restrict__ vh, const float* __restrict__ rel,
                  const int* __restrict__ rel_ids, const int* __restrict__ mask,
                  __half* __restrict__ ctxh, __half* __restrict__ ctxl)
{
    extern __shared__ __half smh[];
    __half*  Qh = smh;                 // [64][72]
    __half*  Ql = smh + 4608;
    __half*  Kh = smh + 9216;          // [128][72]
    __half*  Kl = smh + 18432;
    __half2* Vh = reinterpret_cast<__half2*>(smh + 27648);  // [64 jp][72 d]
    float*   rels = reinterpret_cast<float*>(smh + 36864);  // [64][33]

    const int tid  = threadIdx.x;
    const int lane = tid & 31;
    const int wid  = tid >> 5;
    const int g = lane >> 2, t = lane & 3;
    const int wm = wid << 4;

    const int i0 = blockIdx.x * 64;
    const int bh = blockIdx.y;
    const int b = bh / HH, hd = bh - b * HH;

    const __half* Qph = qh + (size_t)b * SS * DD + hd * DHH;
    const __half* Qpl = ql + (size_t)b * SS * DD + hd * DHH;
    const __half* Kph = kh + (size_t)b * SS * DD + hd * DHH;
    const __half* Kpl = kl + (size_t)b * SS * DD + hd * DHH;
    const __half* Vp  = vh + (size_t)b * SS * DD + hd * DHH;

    // Q tile -> smem
    {
        int row = tid & 63;
        int base = (tid >> 6) * 8;
        #pragma unroll
        for (int e = 0; e < 8; e++) {
            int dq = (base + e) * 4;
            size_t off = (size_t)(i0 + row) * DD + dq;
            *reinterpret_cast<uint2*>(Qh + row * 72 + dq) = *reinterpret_cast<const uint2*>(Qph + off);
            *reinterpret_cast<uint2*>(Ql + row * 72 + dq) = *reinterpret_cast<const uint2*>(Qpl + off);
        }
    }
    // rel rows -> rels[row][r]
    {
        const float* rp = rel + ((size_t)bh * SS + i0) * RELV;
        #pragma unroll
        for (int e = 0; e < 4; e++) {
            int f = tid + e * 128;
            float4 val = *reinterpret_cast<const float4*>(rp + f * 4);
            int row = f >> 3, r = (f & 7) * 4;
            rels[row * 33 + r + 0] = val.x;
            rels[row * 33 + r + 1] = val.y;
            rels[row * 33 + r + 2] = val.z;
            rels[row * 33 + r + 3] = val.w;
        }
    }
    __syncthreads();

    // Hoisted Q fragments
    uint32_t qfh[4][4], qfl[4][4];
    #pragma unroll
    for (int kc = 0; kc < 4; kc++) {
        int kb = kc * 16;
        const __half* r0h = Qh + (wm + g) * 72 + kb;
        const __half* r8h = r0h + 8 * 72;
        qfh[kc][0] = ldh2(r0h + 2 * t);
        qfh[kc][1] = ldh2(r8h + 2 * t);
        qfh[kc][2] = ldh2(r0h + 2 * t + 8);
        qfh[kc][3] = ldh2(r8h + 2 * t + 8);
        const __half* r0l = Ql + (wm + g) * 72 + kb;
        const __half* r8l = r0l + 8 * 72;
        qfl[kc][0] = ldh2(r0l + 2 * t);
        qfl[kc][1] = ldh2(r8l + 2 * t);
        qfl[kc][2] = ldh2(r0l + 2 * t + 8);
        qfl[kc][3] = ldh2(r8l + 2 * t + 8);
    }

    float m0r = -1e30f, m1r = -1e30f;
    float l0r = 0.f, l1r = 0.f;
    float oacc[8][4];
    #pragma unroll
    for (int nt = 0; nt < 8; nt++) {
        oacc[nt][0] = 0.f; oacc[nt][1] = 0.f; oacc[nt][2] = 0.f; oacc[nt][3] = 0.f;
    }

    const int ig0 = i0 + wm + g;
    const int ig1 = ig0 + 8;
    const int* rid0 = rel_ids + ((size_t)b * SS + ig0) * SS + 2 * t;
    const int* rid1 = rel_ids + ((size_t)b * SS + ig1) * SS + 2 * t;
    const int* mk0  = mask    + ((size_t)b * SS + ig0) * SS + 2 * t;
    const int* mk1  = mask    + ((size_t)b * SS + ig1) * SS + 2 * t;
    const float* rl0 = rels + (wm + g) * 33;
    const float* rl1 = rl0 + 8 * 33;

    for (int jt = 0; jt < 8; jt++) {
        const int j0 = jt * 128;
        __syncthreads();
        // K tile
        #pragma unroll
        for (int e = 0; e < 16; e++) {
            int dq = e * 4;
            size_t off = (size_t)(j0 + tid) * DD + dq;
            *reinterpret_cast<uint2*>(Kh + tid * 72 + dq) = *reinterpret_cast<const uint2*>(Kph + off);
            *reinterpret_cast<uint2*>(Kl + tid * 72 + dq) = *reinterpret_cast<const uint2*>(Kpl + off);
        }
        // V tile: interleave row pairs
        #pragma unroll
        for (int e = 0; e < 8; e++) {
            int f = tid + e * 128;
            int jp = f >> 4, dq = (f & 15) * 4;
            uint2 a = *reinterpret_cast<const uint2*>(Vp + (size_t)(j0 + 2 * jp) * DD + dq);
            uint2 c = *reinterpret_cast<const uint2*>(Vp + (size_t)(j0 + 2 * jp + 1) * DD + dq);
            __half2 ax = *reinterpret_cast<__half2*>(&a.x);
            __half2 ay = *reinterpret_cast<__half2*>(&a.y);
            __half2 cx = *reinterpret_cast<__half2*>(&c.x);
            __half2 cy = *reinterpret_cast<__half2*>(&c.y);
            __half2* dst = Vh + jp * 72 + dq;
            dst[0] = __lows2half2 (ax, cx);
            dst[1] = __highs2half2(ax, cx);
            dst[2] = __lows2half2 (ay, cy);
            dst[3] = __highs2half2(ay, cy);
        }
        __syncthreads();

        // S = Q K^T (fp16x3)
        float sacc[16][4];
        #pragma unroll
        for (int nt = 0; nt < 16; nt++) {
            sacc[nt][0] = 0.f; sacc[nt][1] = 0.f; sacc[nt][2] = 0.f; sacc[nt][3] = 0.f;
        }
        #pragma unroll
        for (int kc = 0; kc < 4; kc++) {
            int kb = kc * 16;
            #pragma unroll
            for (int nt = 0; nt < 16; nt++) {
                const __half* nbh = Kh + (nt * 8 + g) * 72 + kb;
                const __half* nbl = Kl + (nt * 8 + g) * 72 + kb;
                uint32_t b0 = ldh2(nbh + 2 * t);
                uint32_t b1 = ldh2(nbh + 2 * t + 8);
                uint32_t c0 = ldh2(nbl + 2 * t);
                uint32_t c1 = ldh2(nbl + 2 * t + 8);
                mma_f16a(sacc[nt], qfh[kc], b0, b1);
                mma_f16a(sacc[nt], qfl[kc], b0, b1);
                mma_f16a(sacc[nt], qfh[kc], c0, c1);
            }
        }

        // rel gather + mask + scale
        float mx0 = -1e30f, mx1 = -1e30f;
        #pragma unroll
        for (int nt = 0; nt < 16; nt++) {
            int jo = j0 + nt * 8;
            int2 i0v = *reinterpret_cast<const int2*>(rid0 + jo);
            int2 i1v = *reinterpret_cast<const int2*>(rid1 + jo);
            int2 m0v = *reinterpret_cast<const int2*>(mk0 + jo);
            int2 m1v = *reinterpret_cast<const int2*>(mk1 + jo);
            sacc[nt][0] = (sacc[nt][0] + rl0[i0v.x]) * 0.125f + (1.f - (float)m0v.x) * -10000.f;
            sacc[nt][1] = (sacc[nt][1] + rl0[i0v.y]) * 0.125f + (1.f - (float)m0v.y) * -10000.f;
            sacc[nt][2] = (sacc[nt][2] + rl1[i1v.x]) * 0.125f + (1.f - (float)m1v.x) * -10000.f;
            sacc[nt][3] = (sacc[nt][3] + rl1[i1v.y]) * 0.125f + (1.f - (float)m1v.y) * -10000.f;
            mx0 = fmaxf(mx0, fmaxf(sacc[nt][0], sacc[nt][1]));
            mx1 = fmaxf(mx1, fmaxf(sacc[nt][2], sacc[nt][3]));
        }
        mx0 = fmaxf(mx0, __shfl_xor_sync(0xffffffffu, mx0, 1));
        mx0 = fmaxf(mx0, __shfl_xor_sync(0xffffffffu, mx0, 2));
        mx1 = fmaxf(mx1, __shfl_xor_sync(0xffffffffu, mx1, 1));
        mx1 = fmaxf(mx1, __shfl_xor_sync(0xffffffffu, mx1, 2));
        float mn0 = fmaxf(m0r, mx0), mn1 = fmaxf(m1r, mx1);
        float al0 = __expf(m0r - mn0), al1 = __expf(m1r - mn1);
        m0r = mn0; m1r = mn1;

        uint32_t ph[16][2];
        float s0 = 0.f, s1 = 0.f;
        #pragma unroll
        for (int nt = 0; nt < 16; nt++) {
            float p0 = __expf(sacc[nt][0] - mn0);
            float p1 = __expf(sacc[nt][1] - mn0);
            float p2 = __expf(sacc[nt][2] - mn1);
            float p3 = __expf(sacc[nt][3] - mn1);
            s0 += p0 + p1; s1 += p2 + p3;
            __half2 h01 = __floats2half2_rn(p0, p1);
            __half2 h23 = __floats2half2_rn(p2, p3);
            ph[nt][0] = *reinterpret_cast<uint32_t*>(&h01);
            ph[nt][1] = *reinterpret_cast<uint32_t*>(&h23);
        }
        l0r = l0r * al0 + s0;
        l1r = l1r * al1 + s1;
        #pragma unroll
        for (int nt = 0; nt < 8; nt++) {
            oacc[nt][0] *= al0; oacc[nt][1] *= al0;
            oacc[nt][2] *= al1; oacc[nt][3] *= al1;
        }
        #pragma unroll
        for (int kc = 0; kc < 8; kc++) {
            uint32_t a0 = ph[2 * kc][0],     a1 = ph[2 * kc][1];
            uint32_t a2 = ph[2 * kc + 1][0], a3 = ph[2 * kc + 1][1];
            #pragma unroll
            for (int nt = 0; nt < 8; nt++) {
                uint32_t b0 = *reinterpret_cast<const uint32_t*>(&Vh[(kc * 8 + t) * 72 + nt * 8 + g]);
                uint32_t b1 = *reinterpret_cast<const uint32_t*>(&Vh[(kc * 8 + t + 4) * 72 + nt * 8 + g]);
                mma_f16(oacc[nt], a0, a1, a2, a3, b0, b1);
            }
        }
    }

    l0r += __shfl_xor_sync(0xffffffffu, l0r, 1);
    l0r += __shfl_xor_sync(0xffffffffu, l0r, 2);
    l1r += __shfl_xor_sync(0xffffffffu, l1r, 1);
    l1r += __shfl_xor_sync(0xffffffffu, l1r, 2);
    float inv0 = 1.f / l0r, inv1 = 1.f / l1r;
    size_t o0 = ((size_t)b * SS + ig0) * DD + hd * DHH + 2 * t;
    size_t o1 = ((size_t)b * SS + ig1) * DD + hd * DHH + 2 * t;
    #pragma unroll
    for (int nt = 0; nt < 8; nt++) {
        float v0 = oacc[nt][0] * inv0, v1 = oacc[nt][1] * inv0;
        float v2 = oacc[nt][2] * inv1, v3 = oacc[nt][3] * inv1;
        __half h0, h1, h2, h3, l0, l1, l2, l3;
        h_split(v0, h0, l0); h_split(v1, h1, l1);
        h_split(v2, h2, l2); h_split(v3, h3, l3);
        *reinterpret_cast<uint32_t*>(&ctxh[o0 + nt * 8]) = pack2(h0, h1);
        *reinterpret_cast<uint32_t*>(&ctxl[o0 + nt * 8]) = pack2(l0, l1);
        *reinterpret_cast<uint32_t*>(&ctxh[o1 + nt * 8]) = pack2(h2, h3);
        *reinterpret_cast<uint32_t*>(&ctxl[o1 + nt * 8]) = pack2(l2, l3);
    }
}

// ---------------------------------------------------------------------------
// Block reduction (256 threads)
// ---------------------------------------------------------------------------
__device__ __forceinline__ float bsum256(float v) {
    __shared__ float sm[8];
    #pragma unroll
    for (int o = 16; o; o >>= 1) v += __shfl_xor_sync(0xffffffffu, v, o);
    if ((threadIdx.x & 31) == 0) sm[threadIdx.x >> 5] = v;
    __syncthreads();
    float r = 0.f;
    #pragma unroll
    for (int i = 0; i < 8; i++) r += sm[i];
    __syncthreads();
    return r;
}

// ---------------------------------------------------------------------------
// Embedding
// ---------------------------------------------------------------------------
__global__ void embed_kernel(const int* __restrict__ token_ids,
                             const int* __restrict__ segment_ids,
                             const int* __restrict__ position_ids,
                             const int* __restrict__ question_mask,
                             const float* __restrict__ tok_emb,
                             const float* __restrict__ seg_emb,
                             float* __restrict__ x)
{
    int row = blockIdx.x;
    int tok = token_ids[row];
    int seg = segment_ids[row];
    int qmi = question_mask[row];
    float qm = (float)qmi;
    int pos = position_ids[row] * qmi;
    float fpos = (float)pos;

    const float* te = tok_emb + (size_t)tok * DD;
    const float* se = seg_emb + (size_t)seg * DD;
    float* xr = x + (size_t)row * DD;

    for (int i = threadIdx.x; i < DD; i += 256) {
        float ex  = (float)(2 * (i >> 1)) * (1.0f / (float)DD);
        float inv = __powf(10000.0f, -ex);
        float ang = fpos * inv;
        float pe  = (i & 1) ? cosf(ang) : sinf(ang);
        xr[i] = te[i] + se[i] + pe * qm;
    }
}

// ---------------------------------------------------------------------------
// LayerNorm -> hi/lo half planes
// ---------------------------------------------------------------------------
__global__ void ln_kernel(const float* __restrict__ x,
                          const float* __restrict__ gamma,
                          const float* __restrict__ beta,
                          __half* __restrict__ oh, __half* __restrict__ ol)
{
    int row = blockIdx.x;
    const float* xr = x + (size_t)row * DD;
    int t = threadIdx.x;
    float v0 = xr[t], v1 = xr[t + 256], v2 = xr[t + 512];

    float s = bsum256(v0 + v1 + v2);
    float mu = s * (1.0f / (float)DD);
    float d0 = v0 - mu, d1 = v1 - mu, d2 = v2 - mu;
    float s2 = bsum256(d0*d0 + d1*d1 + d2*d2);
    float rstd = rsqrtf(s2 * (1.0f / (float)DD) + 1e-12f);

    float r0 = d0 * rstd * gamma[t]       + beta[t];
    float r1 = d1 * rstd * gamma[t + 256] + beta[t + 256];
    float r2 = d2 * rstd * gamma[t + 512] + beta[t + 512];
    __half h0, h1, h2, l0, l1, l2;
    h_split(r0, h0, l0); h_split(r1, h1, l1); h_split(r2, h2, l2);
    size_t base = (size_t)row * DD;
    oh[base + t]       = h0; ol[base + t]       = l0;
    oh[base + t + 256] = h1; ol[base + t + 256] = l1;
    oh[base + t + 512] = h2; ol[base + t + 512] = l2;
}

// ---------------------------------------------------------------------------
// Relative bias: rel[bh,i,r] = sum_d q[b,i,h,d] * rel_emb[r,h,d]
// 32 i-rows per block; warp lane = r (conflict-free), warp id = i-group.
// ---------------------------------------------------------------------------
__global__ __launch_bounds__(256, 4)
void rel_kernel(const __half* __restrict__ qh,
                const __half* __restrict__ ql,
                const float* __restrict__ relw,
                float* __restrict__ rel)
{
    int bh = blockIdx.y;
    int b = bh / HH, h = bh % HH;
    int i0 = blockIdx.x * 32;

    __shared__ float Rs[RELV][65];
    __shared__ float Qs[32][65];

    int tid = threadIdx.x;
    // Rs: 32x64 floats
    #pragma unroll
    for (int e = 0; e < 8; e++) {
        int idx = tid + e * 256;
        int r = idx >> 6, d = idx & 63;
        Rs[r][d] = relw[((size_t)r * HH + h) * DHH + d];
    }
    // Qs: 32 rows x 64 d (hi+lo recombined)
    #pragma unroll
    for (int e = 0; e < 8; e++) {
        int idx = tid + e * 256;
        int ii = idx >> 6, d = idx & 63;
        size_t off = (size_t)b * SS * DD + (size_t)(i0 + ii) * DD + h * DHH + d;
        Qs[ii][d] = __half2float(qh[off]) + __half2float(ql[off]);
    }
    __syncthreads();

    int r = tid & 31, wq = tid >> 5;       // 8 warps -> 8 i-groups
    #pragma unroll
    for (int e = 0; e < 4; e++) {
        int iy = wq + e * 8;
        float s = 0.f;
        #pragma unroll
        for (int d = 0; d < 64; d++) s += Qs[iy][d] * Rs[r][d];
        rel[((size_t)bh * SS + i0 + iy) * RELV + r] = s;
    }
}

// ---------------------------------------------------------------------------
// Launch
// ---------------------------------------------------------------------------
extern "C" void kernel_launch(void* const* d_in, const int* in_sizes, int n_in,
                              void* d_out, int out_size)
{
    const int* token_ids     = (const int*)d_in[0];
    const int* segment_ids   = (const int*)d_in[1];
    const int* position_ids  = (const int*)d_in[2];
    const int* question_mask = (const int*)d_in[3];
    const int* attention_mask= (const int*)d_in[4];
    const int* rel_ids       = (const int*)d_in[5];
    const float* tok_emb = (const float*)d_in[6];
    const float* seg_emb = (const float*)d_in[7];
    const float* ln1_g = (const float*)d_in[8];
    const float* ln1_b = (const float*)d_in[9];
    const float* ln2_g = (const float*)d_in[10];
    const float* ln2_b = (const float*)d_in[11];
    const float* wq = (const float*)d_in[12];
    const float* bq = (const float*)d_in[13];
    const float* wk = (const float*)d_in[14];
    const float* bk = (const float*)d_in[15];
    const float* wv = (const float*)d_in[16];
    const float* bv = (const float*)d_in[17];
    const float* wo = (const float*)d_in[18];
    const float* bo = (const float*)d_in[19];
    const float* rel_emb = (const float*)d_in[20];
    const float* w1 = (const float*)d_in[21];
    const float* b1 = (const float*)d_in[22];
    const float* w2 = (const float*)d_in[23];
    const float* b2 = (const float*)d_in[24];

    float *x, *rl;
    __half *hh, *hl, *qh, *ql, *kh, *kl, *vh, *ch, *cl, *ffh, *ffl, *wh, *wl;
    cudaGetSymbolAddress((void**)&x,   g_x);
    cudaGetSymbolAddress((void**)&rl,  g_rel);
    cudaGetSymbolAddress((void**)&hh,  g_hh);
    cudaGetSymbolAddress((void**)&hl,  g_hl);
    cudaGetSymbolAddress((void**)&qh,  g_qh);
    cudaGetSymbolAddress((void**)&ql,  g_ql);
    cudaGetSymbolAddress((void**)&kh,  g_kh);
    cudaGetSymbolAddress((void**)&kl,  g_kl);
    cudaGetSymbolAddress((void**)&vh,  g_vh);
    cudaGetSymbolAddress((void**)&ch,  g_ch);
    cudaGetSymbolAddress((void**)&cl,  g_cl);
    cudaGetSymbolAddress((void**)&ffh, g_ffh);
    cudaGetSymbolAddress((void**)&ffl, g_ffl);
    cudaGetSymbolAddress((void**)&wh,  g_wh);
    cudaGetSymbolAddress((void**)&wl,  g_wl);

    const int FLASH_SMEM = 82176;
    cudaFuncSetAttribute(flash_kernel,
                         cudaFuncAttributeMaxDynamicSharedMemorySize, FLASH_SMEM);

    // Pre-split all weights into hi/lo half planes
    {
        int n4;
        n4 = WDD / 4;
        split_kernel<<<(n4 + 255) / 256, 256>>>(wq, wh + OFF_WQ, wl + OFF_WQ, n4);
        split_kernel<<<(n4 + 255) / 256, 256>>>(wk, wh + OFF_WK, wl + OFF_WK, n4);
        split_kernel<<<(n4 + 255) / 256, 256>>>(wv, wh + OFF_WV, wl + OFF_WV, n4);
        split_kernel<<<(n4 + 255) / 256, 256>>>(wo, wh + OFF_WO, wl + OFF_WO, n4);
        n4 = WDF / 4;
        split_kernel<<<(n4 + 255) / 256, 256>>>(w1, wh + OFF_W1, wl + OFF_W1, n4);
        split_kernel<<<(n4 + 255) / 256, 256>>>(w2, wh + OFF_W2, wl + OFF_W2, n4);
    }

    embed_kernel<<<NROW, 256>>>(token_ids, segment_ids, position_ids,
                                question_mask, tok_emb, seg_emb, x);

    for (int l = 0; l < LL; l++) {
        size_t odd = (size_t)l * DD * DD;
        size_t odf = (size_t)l * DD * FF;

        // --- attention block ---
        ln_kernel<<<NROW, 256>>>(x, ln1_g + l * DD, ln1_b + l * DD, hh, hl);

        qkv_kernel<<<dim3(DD / 128, NROW / 128, 3), 256>>>(
            hh, hl,
            wh + OFF_WQ + odd, wl + OFF_WQ + odd,
            wh + OFF_WK + odd, wl + OFF_WK + odd,
            wh + OFF_WV + odd, wl + OFF_WV + odd,
            bq + l * DD, bk + l * DD, bv + l * DD,
            qh, ql, kh, kl, vh);

        rel_kernel<<<dim3(SS / 32, BB * HH), 256>>>(
            qh, ql, rel_emb + (size_t)l * RELV * HH * DHH, rl);

        flash_kernel<<<dim3(SS / 64, BB * HH), 128, FLASH_SMEM>>>(
            qh, ql, kh, kl, vh, rl, rel_ids, attention_mask, ch, cl);

        // O-proj: BM=64,BN=128 -> grid (6,32)=192 CTAs, occ 2
        mm_kernel<64,128,32,32,2,0><<<dim3(DD / 128, NROW / 64), 256>>>(
            ch, cl, DD, wh + OFF_WO + odd, wl + OFF_WO + odd, DD,
            bo + l * DD, x, DD, x, nullptr, nullptr, DD, DD);

        // --- FFN block ---
        ln_kernel<<<NROW, 256>>>(x, ln2_g + l * DD, ln2_b + l * DD, hh, hl);
        mm_kernel<128,128,64,32,1,1><<<dim3(FF / 128, NROW / 128), 256>>>(
            hh, hl, DD, wh + OFF_W1 + odf, wl + OFF_W1 + odf, FF,
            b1 + l * FF, nullptr, 0, nullptr, ffh, ffl, FF, DD);

        float* outp = (l == LL - 1) ? (float*)d_out : x;
        // FFN2: BM=64,BN=128 -> grid (6,32)=192 CTAs, occ 2
        mm_kernel<64,128,32,32,2,0><<<dim3(DD / 128, NROW / 64), 256>>>(
            ffh, ffl, FF, wh + OFF_W2 + odf, wl + OFF_W2 + odf, DD,
            b2 + l * DD, x, DD, outp, nullptr, nullptr, DD, FF);
    }
}

// round 7
// speedup vs baseline: 1.2624x; 1.1832x over previous
#include <cuda_runtime.h>
#include <cuda_fp16.h>
#include <math.h>
#include <stdint.h>

// Problem constants
#define BB   2
#define SS   1024
#define DD   768
#define HH   12
#define DHH  64
#define LL   6
#define FF   3072
#define RELV 32
#define NROW (BB*SS)          // 2048 token rows

// ---------------------------------------------------------------------------
// Scratch (device globals; no dynamic allocation allowed)
// ---------------------------------------------------------------------------
__device__ float g_x  [NROW*DD];
__device__ float g_h  [NROW*DD];
__device__ float g_q  [NROW*DD];
__device__ float g_k  [NROW*DD];
__device__ float g_v  [NROW*DD];
__device__ float g_ctx[NROW*DD];
__device__ float g_rel[(size_t)BB*HH*SS*RELV];
__device__ float g_ffn[(size_t)NROW*FF];

// ---------------------------------------------------------------------------
// fp16 helpers
// ---------------------------------------------------------------------------
__device__ __forceinline__ void h_split(float v, __half& hi, __half& lo) {
    hi = __float2half_rn(v);
    lo = __float2half_rn(v - __half2float(hi));
}

__device__ __forceinline__ uint32_t ldh2(const __half* p) {
    return *reinterpret_cast<const uint32_t*>(p);
}

__device__ __forceinline__ void mma_f16(float c[4], uint32_t a0, uint32_t a1,
                                        uint32_t a2, uint32_t a3,
                                        uint32_t b0, uint32_t b1) {
    asm volatile(
        "mma.sync.aligned.m16n8k16.row.col.f32.f16.f16.f32 "
        "{%0,%1,%2,%3},{%4,%5,%6,%7},{%8,%9},{%0,%1,%2,%3};"
        : "+f"(c[0]), "+f"(c[1]), "+f"(c[2]), "+f"(c[3])
        : "r"(a0), "r"(a1), "r"(a2), "r"(a3), "r"(b0), "r"(b1));
}

__device__ __forceinline__ void mma_f16a(float c[4], const uint32_t a[4],
                                         uint32_t b0, uint32_t b1) {
    mma_f16(c, a[0], a[1], a[2], a[3], b0, b1);
}

__device__ __forceinline__ void ldsm4t(uint32_t& r0, uint32_t& r1,
                                       uint32_t& r2, uint32_t& r3, uint32_t a) {
    asm volatile("ldmatrix.sync.aligned.m8n8.x4.trans.shared.b16 {%0,%1,%2,%3}, [%4];"
                 : "=r"(r0), "=r"(r1), "=r"(r2), "=r"(r3) : "r"(a));
}

__device__ __forceinline__ float gelu_tanh(float v) {
    float u = 0.7978845608028654f * (v + 0.044715f * v * v * v);
    return 0.5f * v * (1.0f + tanhf(u));
}

// ---------------------------------------------------------------------------
// Tensor-core GEMM core: fp16x3 split (C += Ah.Bh + Al.Bh + Ah.Bl) => ~fp32
// C[M,N] = A[M,K] @ B[K,N] + epilogue. Block 256 thr = 8 warps. BK=16.
// A in smem as [m][k] half (direct half2 fragment loads, conflict-free);
// B in smem as [k][n] half, fragments via ldmatrix.x4.trans.
// EPI: 0=+bias, 1=+bias+gelu, 2=+bias+residual
// ---------------------------------------------------------------------------
template<int BM, int BN, int WM, int WN, int EPI>
__device__ __forceinline__ void gemm_core(
    const float* __restrict__ A, int lda,
    const float* __restrict__ B, int ldb,
    const float* __restrict__ bias,
    const float* __restrict__ R, int ldr,
    float* __restrict__ C, int ldc,
    int K, int m0, int n0)
{
    constexpr int NWN = BN / WN;
    constexpr int NMT = WM / 16;
    constexpr int NNT = WN / 8;
    constexpr int NA4 = (BM * 16) / 1024;
    constexpr int NB4 = (BN * 16) / 1024;
    constexpr int AKP = 24;              // halfs per A row (16 + 8 pad)
    constexpr int BNP = BN + 8;          // halfs per B row
    constexpr int ASZ = BM * AKP;
    constexpr int BSZ = 16 * BNP;

    __shared__ __align__(16) __half sh[2 * ASZ + 2 * BSZ];
    __half* Ah = sh;
    __half* Al = sh + ASZ;
    __half* Bh = sh + 2 * ASZ;
    __half* Bl = sh + 2 * ASZ + BSZ;

    const int tid  = threadIdx.x;
    const int lane = tid & 31;
    const int wid  = tid >> 5;
    const int g    = lane >> 2;
    const int t    = lane & 3;
    const int wm   = (wid / NWN) * WM;
    const int wn   = (wid % NWN) * WN;

    const int lk    = ((lane >> 3) & 1) * 8 + (lane & 7);
    const int lncol = ((lane >> 4) & 1) * 8;
    const uint32_t bhb = (uint32_t)__cvta_generic_to_shared(Bh);
    const uint32_t blb = (uint32_t)__cvta_generic_to_shared(Bl);

    const float* Ap = A + (size_t)m0 * lda;
    const float* Bp = B + n0;

    float acc[NMT][NNT][4];
    #pragma unroll
    for (int i = 0; i < NMT; i++)
        #pragma unroll
        for (int j = 0; j < NNT; j++)
            #pragma unroll
            for (int e = 0; e < 4; e++) acc[i][j][e] = 0.f;

    float4 rA[NA4], rB[NB4];

    auto gload = [&](int k0) {
        #pragma unroll
        for (int e = 0; e < NA4; e++) {
            int f = tid + e * 256;
            rA[e] = *reinterpret_cast<const float4*>(
                Ap + (size_t)(f >> 2) * lda + k0 + (f & 3) * 4);
        }
        #pragma unroll
        for (int e = 0; e < NB4; e++) {
            int f = tid + e * 256;
            rB[e] = *reinterpret_cast<const float4*>(
                Bp + (size_t)(k0 + f / (BN / 4)) * ldb + (f % (BN / 4)) * 4);
        }
    };

    auto sstore = [&]() {
        #pragma unroll
        for (int e = 0; e < NA4; e++) {
            int f = tid + e * 256; int m = f >> 2; int kq = (f & 3) * 4;
            float vv[4] = {rA[e].x, rA[e].y, rA[e].z, rA[e].w};
            __half hh[4], ll[4];
            #pragma unroll
            for (int i = 0; i < 4; i++) h_split(vv[i], hh[i], ll[i]);
            __half* pa = Ah + m * AKP + kq;
            __half* pl = Al + m * AKP + kq;
            *reinterpret_cast<__half2*>(pa)     = __halves2half2(hh[0], hh[1]);
            *reinterpret_cast<__half2*>(pa + 2) = __halves2half2(hh[2], hh[3]);
            *reinterpret_cast<__half2*>(pl)     = __halves2half2(ll[0], ll[1]);
            *reinterpret_cast<__half2*>(pl + 2) = __halves2half2(ll[2], ll[3]);
        }
        #pragma unroll
        for (int e = 0; e < NB4; e++) {
            int f = tid + e * 256; int kk = f / (BN / 4); int nq = (f % (BN / 4)) * 4;
            float vv[4] = {rB[e].x, rB[e].y, rB[e].z, rB[e].w};
            __half hh[4], ll[4];
            #pragma unroll
            for (int i = 0; i < 4; i++) h_split(vv[i], hh[i], ll[i]);
            __half* pb = Bh + kk * BNP + nq;
            __half* pl = Bl + kk * BNP + nq;
            *reinterpret_cast<__half2*>(pb)     = __halves2half2(hh[0], hh[1]);
            *reinterpret_cast<__half2*>(pb + 2) = __halves2half2(hh[2], hh[3]);
            *reinterpret_cast<__half2*>(pl)     = __halves2half2(ll[0], ll[1]);
            *reinterpret_cast<__half2*>(pl + 2) = __halves2half2(ll[2], ll[3]);
        }
    };

    gload(0);
    sstore();
    __syncthreads();

    const int ntiles = K >> 4;
    for (int kt = 0; kt < ntiles; kt++) {
        const bool more = (kt + 1 < ntiles);
        if (more) gload((kt + 1) << 4);

        uint32_t ah[NMT][4], al[NMT][4];
        #pragma unroll
        for (int mt = 0; mt < NMT; mt++) {
            int r = wm + mt * 16 + g;
            const __half* Ar  = Ah + r * AKP;
            const __half* Ar8 = Ah + (r + 8) * AKP;
            ah[mt][0] = ldh2(Ar  + 2 * t);
            ah[mt][1] = ldh2(Ar8 + 2 * t);
            ah[mt][2] = ldh2(Ar  + 2 * t + 8);
            ah[mt][3] = ldh2(Ar8 + 2 * t + 8);
            const __half* Lr  = Al + r * AKP;
            const __half* Lr8 = Al + (r + 8) * AKP;
            al[mt][0] = ldh2(Lr  + 2 * t);
            al[mt][1] = ldh2(Lr8 + 2 * t);
            al[mt][2] = ldh2(Lr  + 2 * t + 8);
            al[mt][3] = ldh2(Lr8 + 2 * t + 8);
        }

        #pragma unroll
        for (int np = 0; np < NNT / 2; np++) {
            uint32_t off = (uint32_t)(lk * BNP + wn + np * 16 + lncol) * 2;
            uint32_t b0, b1, b2, b3, c0, c1, c2, c3;
            ldsm4t(b0, b1, b2, b3, bhb + off);
            ldsm4t(c0, c1, c2, c3, blb + off);
            #pragma unroll
            for (int mt = 0; mt < NMT; mt++) {
                mma_f16a(acc[mt][2 * np],     ah[mt], b0, b1);
                mma_f16a(acc[mt][2 * np],     al[mt], b0, b1);
                mma_f16a(acc[mt][2 * np],     ah[mt], c0, c1);
                mma_f16a(acc[mt][2 * np + 1], ah[mt], b2, b3);
                mma_f16a(acc[mt][2 * np + 1], al[mt], b2, b3);
                mma_f16a(acc[mt][2 * np + 1], ah[mt], c2, c3);
            }
        }
        __syncthreads();
        if (more) { sstore(); __syncthreads(); }
    }

    // Epilogue
    #pragma unroll
    for (int mt = 0; mt < NMT; mt++) {
        int r0 = m0 + wm + mt * 16 + g;
        #pragma unroll
        for (int nt = 0; nt < NNT; nt++) {
            int cc = n0 + wn + nt * 8 + t * 2;
            float2 p0 = make_float2(acc[mt][nt][0], acc[mt][nt][1]);
            float2 p1 = make_float2(acc[mt][nt][2], acc[mt][nt][3]);
            float b0 = bias[cc], b1 = bias[cc + 1];
            p0.x += b0; p0.y += b1; p1.x += b0; p1.y += b1;
            if (EPI == 1) {
                p0.x = gelu_tanh(p0.x); p0.y = gelu_tanh(p0.y);
                p1.x = gelu_tanh(p1.x); p1.y = gelu_tanh(p1.y);
            }
            if (EPI == 2) {
                p0.x += R[(size_t)r0 * ldr + cc];
                p0.y += R[(size_t)r0 * ldr + cc + 1];
                p1.x += R[(size_t)(r0 + 8) * ldr + cc];
                p1.y += R[(size_t)(r0 + 8) * ldr + cc + 1];
            }
            *reinterpret_cast<float2*>(&C[(size_t)r0 * ldc + cc]) = p0;
            *reinterpret_cast<float2*>(&C[(size_t)(r0 + 8) * ldc + cc]) = p1;
        }
    }
}

// QKV fused via blockIdx.z
__global__ __launch_bounds__(256, 1)
void qkv_kernel(const float* __restrict__ h,
                const float* __restrict__ wq, const float* __restrict__ wk,
                const float* __restrict__ wv,
                const float* __restrict__ bq, const float* __restrict__ bk,
                const float* __restrict__ bv,
                float* __restrict__ q, float* __restrict__ k, float* __restrict__ v)
{
    int z = blockIdx.z;
    const float* W  = (z == 0) ? wq : (z == 1) ? wk : wv;
    const float* bi = (z == 0) ? bq : (z == 1) ? bk : bv;
    float* C        = (z == 0) ? q  : (z == 1) ? k  : v;
    gemm_core<128,128,64,32,0>(h, DD, W, DD, bi, nullptr, 0, C, DD,
                               DD, blockIdx.y * 128, blockIdx.x * 128);
}

template<int BM, int BN, int WM, int WN, int EPI>
__global__ __launch_bounds__(256, (BM == 64) ? 2 : 1)
void mm_kernel(const float* __restrict__ A, int lda,
               const float* __restrict__ B, int ldb,
               const float* __restrict__ bias,
               const float* __restrict__ R, int ldr,
               float* __restrict__ C, int ldc, int K)
{
    gemm_core<BM,BN,WM,WN,EPI>(A, lda, B, ldb, bias, R, ldr, C, ldc,
                               K, blockIdx.y * BM, blockIdx.x * BN);
}

// ---------------------------------------------------------------------------
// Fused flash attention: per CTA = 64 query rows of one (b,h).
// 128 threads = 4 warps, warp tile 16(i) x 128(j). Online softmax.
// S = QK^T via fp16x3 split; P.V via fp16 with register-resident P.
// ---------------------------------------------------------------------------
__global__ __launch_bounds__(128, 2)
void flash_kernel(const float* __restrict__ q, const float* __restrict__ k,
                  const float* __restrict__ v, const float* __restrict__ rel,
                  const int* __restrict__ rel_ids, const int* __restrict__ mask,
                  float* __restrict__ ctx)
{
    extern __shared__ float smf[];
    __half*  Qh = reinterpret_cast<__half*>(smf);            // [64][72] halfs
    __half*  Ql = Qh + 4608;
    __half*  Kh = Ql + 4608;                                 // [128][72] halfs
    __half*  Kl = Kh + 9216;
    __half2* Vh = reinterpret_cast<__half2*>(Kl + 9216);     // [64 jp][72 d]
    float*   rels = reinterpret_cast<float*>(Vh + 4608);     // [64][33]

    const int tid  = threadIdx.x;
    const int lane = tid & 31;
    const int wid  = tid >> 5;
    const int g = lane >> 2, t = lane & 3;
    const int wm = wid << 4;

    const int i0 = blockIdx.x * 64;
    const int bh = blockIdx.y;
    const int b = bh / HH, h = bh - b * HH;

    const float* Qp = q + (size_t)b * SS * DD + h * DHH;
    const float* Kp = k + (size_t)b * SS * DD + h * DHH;
    const float* Vp = v + (size_t)b * SS * DD + h * DHH;

    // Q tile -> Qh/Ql [row][d]
    {
        int row = tid & 63;
        int base = (tid >> 6) * 8;
        #pragma unroll
        for (int e = 0; e < 8; e++) {
            int dq = (base + e) * 4;
            float4 val = *reinterpret_cast<const float4*>(Qp + (size_t)(i0 + row) * DD + dq);
            float vv[4] = {val.x, val.y, val.z, val.w};
            __half hh[4], ll[4];
            #pragma unroll
            for (int i = 0; i < 4; i++) h_split(vv[i], hh[i], ll[i]);
            __half* ph = Qh + row * 72 + dq;
            __half* pl = Ql + row * 72 + dq;
            *reinterpret_cast<__half2*>(ph)     = __halves2half2(hh[0], hh[1]);
            *reinterpret_cast<__half2*>(ph + 2) = __halves2half2(hh[2], hh[3]);
            *reinterpret_cast<__half2*>(pl)     = __halves2half2(ll[0], ll[1]);
            *reinterpret_cast<__half2*>(pl + 2) = __halves2half2(ll[2], ll[3]);
        }
    }
    // rel rows (precomputed) -> rels[row][r]
    {
        const float* rp = rel + ((size_t)bh * SS + i0) * RELV;
        #pragma unroll
        for (int e = 0; e < 4; e++) {
            int f = tid + e * 128;
            float4 val = *reinterpret_cast<const float4*>(rp + f * 4);
            int row = f >> 3, r = (f & 7) * 4;
            rels[row * 33 + r + 0] = val.x;
            rels[row * 33 + r + 1] = val.y;
            rels[row * 33 + r + 2] = val.z;
            rels[row * 33 + r + 3] = val.w;
        }
    }
    __syncthreads();

    // Hoisted Q fragments (4 k16 chunks)
    uint32_t qfh[4][4], qfl[4][4];
    #pragma unroll
    for (int kc = 0; kc < 4; kc++) {
        int kb = kc * 16;
        const __half* r0h = Qh + (wm + g) * 72 + kb;
        const __half* r8h = r0h + 8 * 72;
        qfh[kc][0] = ldh2(r0h + 2 * t);
        qfh[kc][1] = ldh2(r8h + 2 * t);
        qfh[kc][2] = ldh2(r0h + 2 * t + 8);
        qfh[kc][3] = ldh2(r8h + 2 * t + 8);
        const __half* r0l = Ql + (wm + g) * 72 + kb;
        const __half* r8l = r0l + 8 * 72;
        qfl[kc][0] = ldh2(r0l + 2 * t);
        qfl[kc][1] = ldh2(r8l + 2 * t);
        qfl[kc][2] = ldh2(r0l + 2 * t + 8);
        qfl[kc][3] = ldh2(r8l + 2 * t + 8);
    }

    float m0r = -1e30f, m1r = -1e30f;
    float l0r = 0.f, l1r = 0.f;
    float oacc[8][4];
    #pragma unroll
    for (int nt = 0; nt < 8; nt++) {
        oacc[nt][0] = 0.f; oacc[nt][1] = 0.f; oacc[nt][2] = 0.f; oacc[nt][3] = 0.f;
    }

    const int ig0 = i0 + wm + g;
    const int ig1 = ig0 + 8;
    const int* rid0 = rel_ids + ((size_t)b * SS + ig0) * SS + 2 * t;
    const int* rid1 = rel_ids + ((size_t)b * SS + ig1) * SS + 2 * t;
    const int* mk0  = mask    + ((size_t)b * SS + ig0) * SS + 2 * t;
    const int* mk1  = mask    + ((size_t)b * SS + ig1) * SS + 2 * t;
    const float* rl0 = rels + (wm + g) * 33;
    const float* rl1 = rl0 + 8 * 33;

    for (int jt = 0; jt < 8; jt++) {
        const int j0 = jt * 128;
        __syncthreads();
        // K tile -> Kh/Kl [j][d]
        #pragma unroll
        for (int e = 0; e < 16; e++) {
            int dq = e * 4;
            float4 val = *reinterpret_cast<const float4*>(Kp + (size_t)(j0 + tid) * DD + dq);
            float vv[4] = {val.x, val.y, val.z, val.w};
            __half hh[4], ll[4];
            #pragma unroll
            for (int i = 0; i < 4; i++) h_split(vv[i], hh[i], ll[i]);
            __half* ph = Kh + tid * 72 + dq;
            __half* pl = Kl + tid * 72 + dq;
            *reinterpret_cast<__half2*>(ph)     = __halves2half2(hh[0], hh[1]);
            *reinterpret_cast<__half2*>(ph + 2) = __halves2half2(hh[2], hh[3]);
            *reinterpret_cast<__half2*>(pl)     = __halves2half2(ll[0], ll[1]);
            *reinterpret_cast<__half2*>(pl + 2) = __halves2half2(ll[2], ll[3]);
        }
        // V tile -> Vh[jpair][d] as half2(v_j, v_{j+1})
        #pragma unroll
        for (int e = 0; e < 8; e++) {
            int f = tid + e * 128;
            int jp = f >> 4, dq = (f & 15) * 4;
            float4 v0 = *reinterpret_cast<const float4*>(Vp + (size_t)(j0 + 2 * jp) * DD + dq);
            float4 v1 = *reinterpret_cast<const float4*>(Vp + (size_t)(j0 + 2 * jp + 1) * DD + dq);
            __half2* dst = Vh + jp * 72 + dq;
            dst[0] = __floats2half2_rn(v0.x, v1.x);
            dst[1] = __floats2half2_rn(v0.y, v1.y);
            dst[2] = __floats2half2_rn(v0.z, v1.z);
            dst[3] = __floats2half2_rn(v0.w, v1.w);
        }
        __syncthreads();

        // S = Q K^T, 16 n8-tiles per warp, fp16x3
        float sacc[16][4];
        #pragma unroll
        for (int nt = 0; nt < 16; nt++) {
            sacc[nt][0] = 0.f; sacc[nt][1] = 0.f; sacc[nt][2] = 0.f; sacc[nt][3] = 0.f;
        }
        #pragma unroll
        for (int kc = 0; kc < 4; kc++) {
            int kb = kc * 16;
            #pragma unroll
            for (int nt = 0; nt < 16; nt++) {
                const __half* nbh = Kh + (nt * 8 + g) * 72 + kb;
                const __half* nbl = Kl + (nt * 8 + g) * 72 + kb;
                uint32_t b0 = ldh2(nbh + 2 * t);
                uint32_t b1 = ldh2(nbh + 2 * t + 8);
                uint32_t c0 = ldh2(nbl + 2 * t);
                uint32_t c1 = ldh2(nbl + 2 * t + 8);
                mma_f16a(sacc[nt], qfh[kc], b0, b1);
                mma_f16a(sacc[nt], qfl[kc], b0, b1);
                mma_f16a(sacc[nt], qfh[kc], c0, c1);
            }
        }

        // rel gather + mask + scale
        float mx0 = -1e30f, mx1 = -1e30f;
        #pragma unroll
        for (int nt = 0; nt < 16; nt++) {
            int jo = j0 + nt * 8;
            int2 i0v = *reinterpret_cast<const int2*>(rid0 + jo);
            int2 i1v = *reinterpret_cast<const int2*>(rid1 + jo);
            int2 m0v = *reinterpret_cast<const int2*>(mk0 + jo);
            int2 m1v = *reinterpret_cast<const int2*>(mk1 + jo);
            sacc[nt][0] = (sacc[nt][0] + rl0[i0v.x]) * 0.125f + (1.f - (float)m0v.x) * -10000.f;
            sacc[nt][1] = (sacc[nt][1] + rl0[i0v.y]) * 0.125f + (1.f - (float)m0v.y) * -10000.f;
            sacc[nt][2] = (sacc[nt][2] + rl1[i1v.x]) * 0.125f + (1.f - (float)m1v.x) * -10000.f;
            sacc[nt][3] = (sacc[nt][3] + rl1[i1v.y]) * 0.125f + (1.f - (float)m1v.y) * -10000.f;
            mx0 = fmaxf(mx0, fmaxf(sacc[nt][0], sacc[nt][1]));
            mx1 = fmaxf(mx1, fmaxf(sacc[nt][2], sacc[nt][3]));
        }
        mx0 = fmaxf(mx0, __shfl_xor_sync(0xffffffffu, mx0, 1));
        mx0 = fmaxf(mx0, __shfl_xor_sync(0xffffffffu, mx0, 2));
        mx1 = fmaxf(mx1, __shfl_xor_sync(0xffffffffu, mx1, 1));
        mx1 = fmaxf(mx1, __shfl_xor_sync(0xffffffffu, mx1, 2));
        float mn0 = fmaxf(m0r, mx0), mn1 = fmaxf(m1r, mx1);
        float al0 = __expf(m0r - mn0), al1 = __expf(m1r - mn1);
        m0r = mn0; m1r = mn1;

        // p = exp(s - m), pack to half2 (A-fragment layout = C-fragment layout)
        uint32_t ph[16][2];
        float s0 = 0.f, s1 = 0.f;
        #pragma unroll
        for (int nt = 0; nt < 16; nt++) {
            float p0 = __expf(sacc[nt][0] - mn0);
            float p1 = __expf(sacc[nt][1] - mn0);
            float p2 = __expf(sacc[nt][2] - mn1);
            float p3 = __expf(sacc[nt][3] - mn1);
            s0 += p0 + p1; s1 += p2 + p3;
            __half2 h01 = __floats2half2_rn(p0, p1);
            __half2 h23 = __floats2half2_rn(p2, p3);
            ph[nt][0] = *reinterpret_cast<uint32_t*>(&h01);
            ph[nt][1] = *reinterpret_cast<uint32_t*>(&h23);
        }
        l0r = l0r * al0 + s0;
        l1r = l1r * al1 + s1;
        #pragma unroll
        for (int nt = 0; nt < 8; nt++) {
            oacc[nt][0] *= al0; oacc[nt][1] *= al0;
            oacc[nt][2] *= al1; oacc[nt][3] *= al1;
        }
        // O += P @ V  (fp16, K=128 in 8 chunks of 16)
        #pragma unroll
        for (int kc = 0; kc < 8; kc++) {
            uint32_t a0 = ph[2 * kc][0],     a1 = ph[2 * kc][1];
            uint32_t a2 = ph[2 * kc + 1][0], a3 = ph[2 * kc + 1][1];
            #pragma unroll
            for (int nt = 0; nt < 8; nt++) {
                uint32_t b0 = *reinterpret_cast<const uint32_t*>(&Vh[(kc * 8 + t) * 72 + nt * 8 + g]);
                uint32_t b1 = *reinterpret_cast<const uint32_t*>(&Vh[(kc * 8 + t + 4) * 72 + nt * 8 + g]);
                mma_f16(oacc[nt], a0, a1, a2, a3, b0, b1);
            }
        }
    }

    // finalize
    l0r += __shfl_xor_sync(0xffffffffu, l0r, 1);
    l0r += __shfl_xor_sync(0xffffffffu, l0r, 2);
    l1r += __shfl_xor_sync(0xffffffffu, l1r, 1);
    l1r += __shfl_xor_sync(0xffffffffu, l1r, 2);
    float inv0 = 1.f / l0r, inv1 = 1.f / l1r;
    float* C0 = ctx + ((size_t)b * SS + ig0) * DD + h * DHH + 2 * t;
    float* C1 = ctx + ((size_t)b * SS + ig1) * DD + h * DHH + 2 * t;
    #pragma unroll
    for (int nt = 0; nt < 8; nt++) {
        *reinterpret_cast<float2*>(C0 + nt * 8) = make_float2(oacc[nt][0] * inv0, oacc[nt][1] * inv0);
        *reinterpret_cast<float2*>(C1 + nt * 8) = make_float2(oacc[nt][2] * inv1, oacc[nt][3] * inv1);
    }
}

// ---------------------------------------------------------------------------
// Block reduction (256 threads)
// ---------------------------------------------------------------------------
__device__ __forceinline__ float bsum256(float v) {
    __shared__ float sm[8];
    #pragma unroll
    for (int o = 16; o; o >>= 1) v += __shfl_xor_sync(0xffffffffu, v, o);
    if ((threadIdx.x & 31) == 0) sm[threadIdx.x >> 5] = v;
    __syncthreads();
    float r = 0.f;
    #pragma unroll
    for (int i = 0; i < 8; i++) r += sm[i];
    __syncthreads();
    return r;
}

// ---------------------------------------------------------------------------
// Embedding
// ---------------------------------------------------------------------------
__global__ void embed_kernel(const int* __restrict__ token_ids,
                             const int* __restrict__ segment_ids,
                             const int* __restrict__ position_ids,
                             const int* __restrict__ question_mask,
                             const float* __restrict__ tok_emb,
                             const float* __restrict__ seg_emb,
                             float* __restrict__ x)
{
    int row = blockIdx.x;
    int tok = token_ids[row];
    int seg = segment_ids[row];
    int qmi = question_mask[row];
    float qm = (float)qmi;
    int pos = position_ids[row] * qmi;
    float fpos = (float)pos;

    const float* te = tok_emb + (size_t)tok * DD;
    const float* se = seg_emb + (size_t)seg * DD;
    float* xr = x + (size_t)row * DD;

    for (int i = threadIdx.x; i < DD; i += 256) {
        float ex  = (float)(2 * (i >> 1)) * (1.0f / (float)DD);
        float inv = __powf(10000.0f, -ex);
        float ang = fpos * inv;
        float pe  = (i & 1) ? cosf(ang) : sinf(ang);
        xr[i] = te[i] + se[i] + pe * qm;
    }
}

// ---------------------------------------------------------------------------
// LayerNorm
// ---------------------------------------------------------------------------
__global__ void ln_kernel(const float* __restrict__ x,
                          const float* __restrict__ gamma,
                          const float* __restrict__ beta,
                          float* __restrict__ out)
{
    int row = blockIdx.x;
    const float* xr = x + (size_t)row * DD;
    int t = threadIdx.x;
    float v0 = xr[t], v1 = xr[t + 256], v2 = xr[t + 512];

    float s = bsum256(v0 + v1 + v2);
    float mu = s * (1.0f / (float)DD);
    float d0 = v0 - mu, d1 = v1 - mu, d2 = v2 - mu;
    float s2 = bsum256(d0*d0 + d1*d1 + d2*d2);
    float var = s2 * (1.0f / (float)DD);
    float rstd = rsqrtf(var + 1e-12f);

    float* orow = out + (size_t)row * DD;
    orow[t]       = d0 * rstd * gamma[t]       + beta[t];
    orow[t + 256] = d1 * rstd * gamma[t + 256] + beta[t + 256];
    orow[t + 512] = d2 * rstd * gamma[t + 512] + beta[t + 512];
}

// ---------------------------------------------------------------------------
// Relative bias: rel[bh,i,r] = sum_d q[b,i,h,d] * rel_emb[r,h,d]
// 32 i-rows per block; lane = r (conflict-free), 4 rows per warp.
// ---------------------------------------------------------------------------
__global__ __launch_bounds__(256, 4)
void rel_kernel(const float* __restrict__ q,
                const float* __restrict__ relw,
                float* __restrict__ rel)
{
    int bh = blockIdx.y;
    int b = bh / HH, h = bh % HH;
    int i0 = blockIdx.x * 32;

    __shared__ float Rs[RELV][65];
    __shared__ float Qs[32][65];

    int tid = threadIdx.x;
    #pragma unroll
    for (int e = 0; e < 8; e++) {
        int idx = tid + e * 256;
        int r = idx >> 6, d = idx & 63;
        Rs[r][d] = relw[((size_t)r * HH + h) * DHH + d];
    }
    #pragma unroll
    for (int e = 0; e < 8; e++) {
        int idx = tid + e * 256;
        int ii = idx >> 6, d = idx & 63;
        Qs[ii][d] = q[(size_t)b * SS * DD + (size_t)(i0 + ii) * DD + h * DHH + d];
    }
    __syncthreads();

    int r = tid & 31, wq = tid >> 5;   // 8 warps
    #pragma unroll
    for (int e = 0; e < 4; e++) {
        int iy = wq + e * 8;
        float s = 0.f;
        #pragma unroll
        for (int d = 0; d < 64; d++) s += Qs[iy][d] * Rs[r][d];
        rel[((size_t)bh * SS + i0 + iy) * RELV + r] = s;
    }
}

// ---------------------------------------------------------------------------
// Launch
// ---------------------------------------------------------------------------
extern "C" void kernel_launch(void* const* d_in, const int* in_sizes, int n_in,
                              void* d_out, int out_size)
{
    const int* token_ids     = (const int*)d_in[0];
    const int* segment_ids   = (const int*)d_in[1];
    const int* position_ids  = (const int*)d_in[2];
    const int* question_mask = (const int*)d_in[3];
    const int* attention_mask= (const int*)d_in[4];
    const int* rel_ids       = (const int*)d_in[5];
    const float* tok_emb = (const float*)d_in[6];
    const float* seg_emb = (const float*)d_in[7];
    const float* ln1_g = (const float*)d_in[8];
    const float* ln1_b = (const float*)d_in[9];
    const float* ln2_g = (const float*)d_in[10];
    const float* ln2_b = (const float*)d_in[11];
    const float* wq = (const float*)d_in[12];
    const float* bq = (const float*)d_in[13];
    const float* wk = (const float*)d_in[14];
    const float* bk = (const float*)d_in[15];
    const float* wv = (const float*)d_in[16];
    const float* bv = (const float*)d_in[17];
    const float* wo = (const float*)d_in[18];
    const float* bo = (const float*)d_in[19];
    const float* rel_emb = (const float*)d_in[20];
    const float* w1 = (const float*)d_in[21];
    const float* b1 = (const float*)d_in[22];
    const float* w2 = (const float*)d_in[23];
    const float* b2 = (const float*)d_in[24];

    float *x, *h, *q, *k, *v, *ctx, *rl, *ff;
    cudaGetSymbolAddress((void**)&x,   g_x);
    cudaGetSymbolAddress((void**)&h,   g_h);
    cudaGetSymbolAddress((void**)&q,   g_q);
    cudaGetSymbolAddress((void**)&k,   g_k);
    cudaGetSymbolAddress((void**)&v,   g_v);
    cudaGetSymbolAddress((void**)&ctx, g_ctx);
    cudaGetSymbolAddress((void**)&rl,  g_rel);
    cudaGetSymbolAddress((void**)&ff,  g_ffn);

    const int FLASH_SMEM = 82176;
    cudaFuncSetAttribute(flash_kernel,
                         cudaFuncAttributeMaxDynamicSharedMemorySize, FLASH_SMEM);

    embed_kernel<<<NROW, 256>>>(token_ids, segment_ids, position_ids,
                                question_mask, tok_emb, seg_emb, x);

    for (int l = 0; l < LL; l++) {
        const float* wq_l = wq + (size_t)l * DD * DD;
        const float* wk_l = wk + (size_t)l * DD * DD;
        const float* wv_l = wv + (size_t)l * DD * DD;
        const float* wo_l = wo + (size_t)l * DD * DD;
        const float* w1_l = w1 + (size_t)l * DD * FF;
        const float* w2_l = w2 + (size_t)l * FF * DD;

        // --- attention block ---
        ln_kernel<<<NROW, 256>>>(x, ln1_g + l * DD, ln1_b + l * DD, h);

        qkv_kernel<<<dim3(DD / 128, NROW / 128, 3), 256>>>(
            h, wq_l, wk_l, wv_l, bq + l * DD, bk + l * DD, bv + l * DD, q, k, v);

        rel_kernel<<<dim3(SS / 32, BB * HH), 256>>>(
            q, rel_emb + (size_t)l * RELV * HH * DHH, rl);

        flash_kernel<<<dim3(SS / 64, BB * HH), 128, FLASH_SMEM>>>(
            q, k, v, rl, rel_ids, attention_mask, ctx);

        // O-proj: BM=64, BN=128 -> grid (6,32)=192 CTAs, occ 2
        mm_kernel<64,128,32,32,2><<<dim3(DD / 128, NROW / 64), 256>>>(
            ctx, DD, wo_l, DD, bo + l * DD, x, DD, x, DD, DD);

        // --- FFN block ---
        ln_kernel<<<NROW, 256>>>(x, ln2_g + l * DD, ln2_b + l * DD, h);
        mm_kernel<128,128,64,32,1><<<dim3(FF / 128, NROW / 128), 256>>>(
            h, DD, w1_l, FF, b1 + l * FF, nullptr, 0, ff, FF, DD);

        float* outp = (l == LL - 1) ? (float*)d_out : x;
        // FFN2: BM=64, BN=128 -> grid (6,32)=192 CTAs, occ 2
        mm_kernel<64,128,32,32,2><<<dim3(DD / 128, NROW / 64), 256>>>(
            ff, FF, w2_l, DD, b2 + l * DD, x, DD, outp, DD, FF);
    }
}